// round 13
// baseline (speedup 1.0000x reference)
#include <cuda_runtime.h>
#include <cuda_bf16.h>
#include <math.h>
#include <stdint.h>

#define NQv   262144
#define EMB   128
#define HWPX  30720
#define IMW   320
#define NIc   300
#define NIM   384
#define HIDN  512
#define NEGV  -1e30f

// ---------------- device scratch ----------------
__device__ float g_full[(size_t)NQv*EMB];
__device__ float g_se  [(size_t)NQv*EMB];
__device__ float g_sp  [(size_t)NQv*EMB];
__device__ float g_bA  [(size_t)NQv*EMB];
__device__ float g_hid [(size_t)NQv*HIDN];

__device__ float g_wx[HWPX], g_wy[HWPX], g_wz[HWPX];
__device__ int   g_kidx[NIc];
__device__ float g_sk[NIc];
__device__ int   g_mids[HWPX];
__device__ int   g_marea[NIc], g_parea[NIc], g_inter[NIc];
__device__ int   g_selj[NIc], g_k2idx[NIc];
__device__ float g_xyz[NIc*3];
__device__ int   g_fidx[NQv];
__device__ int   g_inv [NQv];
__device__ int   g_bcnt[512], g_boff[512];
__device__ int   g_ints[8];   // 0=Nk 1=Ns 2=Nf 3=fovmode

__device__ float gi_q[NIM*EMB], gi_p[NIM*EMB], gi_qin[NIM*EMB], gi_Qp[NIM*EMB],
                 gi_Kp[NIM*EMB], gi_Vp[NIM*EMB];

// attn0 split-K partials
__device__ float g_pm  [4*NIM*16];
__device__ float g_pl  [4*NIM*16];
__device__ float g_pacc[4*NIM*16*32];

// ---------------- fov dtype auto-detect ----------------
__global__ void k_fovdetect(const unsigned int* __restrict__ fm){
    __shared__ int fl[6];
    if (threadIdx.x < 6) fl[threadIdx.x] = 0;
    __syncthreads();
    for (int i = threadIdx.x; i < 32768; i += 256){
        unsigned w = fm[i];
        if (w > 1u)                      atomicOr(&fl[0], 1);
        if (w != 0u && w != 0x3f800000u) atomicOr(&fl[1], 1);
        unsigned b0=w&255u,b1=(w>>8)&255u,b2=(w>>16)&255u,b3=w>>24;
        if (b0>1u||b1>1u||b2>1u||b3>1u)  atomicOr(&fl[2], 1);
        if ((i & 1) && w)                atomicOr(&fl[3], 1);
    }
    __syncthreads();
    if (threadIdx.x == 0){
        int mode;
        if      (!fl[0]) mode = fl[3] ? 0 : 1;
        else if (!fl[1]) mode = 2;
        else if (!fl[2]) mode = 4;
        else             mode = 3;
        g_ints[3] = mode;
    }
}

__device__ __forceinline__ int fov_get(const void* fm, int n){
    switch (g_ints[3]){
        case 0:  return ((const int*)fm)[n] != 0;
        case 1:  return ((const long long*)fm)[n] != 0;
        case 2:  return ((const float*)fm)[n] != 0.f;
        case 3:  return ((const double*)fm)[n] != 0.0;
        default: return ((const unsigned char*)fm)[n] != 0;
    }
}

// ---------------- fov compaction ----------------
__global__ void k_fovcount(const void* __restrict__ fm){
    int idx = blockIdx.x*512 + threadIdx.x;
    int f = fov_get(fm, idx);
    int c = __syncthreads_count(f);
    if (threadIdx.x==0) g_bcnt[blockIdx.x]=c;
}
__global__ void k_fovscan(){
    __shared__ int s[512];
    int t=threadIdx.x;
    int mine=g_bcnt[t];
    s[t]=mine; __syncthreads();
    for (int off=1; off<512; off<<=1){
        int v = (t>=off) ? s[t-off] : 0;
        __syncthreads(); s[t]+=v; __syncthreads();
    }
    g_boff[t]=s[t]-mine;
    if (t==511) g_ints[2]=s[511];
}
__global__ void k_fovscatter(const void* __restrict__ fm){
    __shared__ int s[512];
    int t=threadIdx.x;
    int idx=blockIdx.x*512+t;
    int f=fov_get(fm, idx);
    s[t]=f; __syncthreads();
    for (int off=1; off<512; off<<=1){
        int v = (t>=off) ? s[t-off] : 0;
        __syncthreads(); s[t]+=v; __syncthreads();
    }
    if (f){
        int r = g_boff[blockIdx.x] + s[t]-1;
        g_fidx[r] = idx;
        g_inv[idx] = r;
    }
}

// ---------------- scene embed base + fused fov gather ----------------
__global__ void k_buildfull(const void* __restrict__ fm,
                            const float* __restrict__ sew, const float* __restrict__ x3d,
                            const float* __restrict__ posw, const float* __restrict__ vo){
    __shared__ float tsh[32][33];
    int n0 = blockIdx.x*32, c0 = blockIdx.y*32;
    int tx = threadIdx.x, ty = threadIdx.y;
    #pragma unroll
    for (int yy=0; yy<32; yy+=8)
        tsh[ty+yy][tx] = x3d[(size_t)(c0+ty+yy)*NQv + n0+tx];
    __syncthreads();
    float v0 = vo[0], v1 = vo[1], v2 = vo[2];
    #pragma unroll
    for (int yy=0; yy<32; yy+=8){
        int n=n0+ty+yy, c=c0+tx;
        float v = sew[(size_t)n*EMB+c] + tsh[tx][ty+yy];
        g_full[(size_t)n*EMB+c] = v;
        if (fov_get(fm, n)){
            int r = g_inv[n];
            g_se[(size_t)r*EMB+c] = v;
            int i = n>>11, j = (n>>4)&127, k = n&15;
            float px=(i+0.5f)*0.2f+v0, py=(j+0.5f)*0.2f+v1, pz=(k+0.5f)*0.2f+v2;
            g_sp[(size_t)r*EMB+c] = posw[c*3+0]*px + posw[c*3+1]*py + posw[c*3+2]*pz;
        }
    }
}

// ---------------- world coords (with inlined matrix inverses) ----------------
__global__ void k_world(const float* __restrict__ depth,
                        const float* __restrict__ Km, const float* __restrict__ Em){
    __shared__ float Ki[9], Ei[16];
    if (threadIdx.x == 0){
        {   double a=Km[0],b=Km[1],c=Km[2],d=Km[3],e=Km[4],f=Km[5],g=Km[6],h=Km[7],i=Km[8];
            double det = a*(e*i-f*h) - b*(d*i-f*g) + c*(d*h-e*g);
            double inv[9] = { e*i-f*h, c*h-b*i, b*f-c*e,
                              f*g-d*i, a*i-c*g, c*d-a*f,
                              d*h-e*g, b*g-a*h, a*e-b*d };
            for (int t=0;t<9;t++) Ki[t] = (float)(inv[t]/det);
        }
        {   double M[4][8];
            for (int i=0;i<4;i++) for (int j=0;j<4;j++){ M[i][j]=Em[i*4+j]; M[i][4+j]=(i==j)?1.0:0.0; }
            for (int col=0; col<4; col++){
                int piv=col;
                for (int r=col+1;r<4;r++) if (fabs(M[r][col])>fabs(M[piv][col])) piv=r;
                if (piv!=col) for (int j=0;j<8;j++){ double t=M[col][j]; M[col][j]=M[piv][j]; M[piv][j]=t; }
                double pv=M[col][col];
                for (int j=0;j<8;j++) M[col][j]/=pv;
                for (int r=0;r<4;r++) if (r!=col){
                    double f=M[r][col];
                    for (int j=0;j<8;j++) M[r][j]-=f*M[col][j];
                }
            }
            for (int i=0;i<4;i++) for (int j=0;j<4;j++) Ei[i*4+j]=(float)M[i][4+j];
        }
    }
    __syncthreads();
    int p = blockIdx.x*256 + threadIdx.x;
    if (p >= HWPX) return;
    int y = p / IMW, x = p % IMW;
    float d = depth[p];
    float vx = (float)x*4.0f*d, vy = (float)y*4.0f*d, vz = d;
    float c0 = Ki[0]*vx + Ki[1]*vy + Ki[2]*vz;
    float c1 = Ki[3]*vx + Ki[4]*vy + Ki[5]*vz;
    float c2 = Ki[6]*vx + Ki[7]*vy + Ki[8]*vz;
    g_wx[p] = Ei[0]*c0 + Ei[1]*c1 + Ei[2] *c2 + Ei[3];
    g_wy[p] = Ei[4]*c0 + Ei[5]*c1 + Ei[6] *c2 + Ei[7];
    g_wz[p] = Ei[8]*c0 + Ei[9]*c1 + Ei[10]*c2 + Ei[11];
}

// ---------------- instance scoring ----------------
__global__ void k_scores(const float* __restrict__ logits){
    __shared__ float sc[NIc];
    __shared__ int   kp[NIc];
    int i = threadIdx.x;
    if (i < NIc){
        float z[21]; float mx = NEGV;
        #pragma unroll
        for (int j=0;j<21;j++){
            float s = 1.f/(1.f+expf(-logits[i*21+j]));
            z[j] = s/0.06f;
            if (z[j]>mx) mx=z[j];
        }
        float sum=0.f, me=0.f;
        #pragma unroll
        for (int j=0;j<21;j++){ float e=expf(z[j]-mx); sum+=e; if (e>me) me=e; }
        float score = me/sum;
        sc[i]=score; kp[i]=(score>0.25f)?1:0;
    }
    __syncthreads();
    if (i==0){
        int c=0;
        for (int j=0;j<NIc;j++) if (kp[j]){ g_kidx[c]=j; g_sk[c]=sc[j]; c++; }
        g_ints[0]=c;
    }
}

__global__ void k_mids(const float* __restrict__ pm){
    int p = blockIdx.x*256 + threadIdx.x;
    if (p >= HWPX) return;
    int Nk = g_ints[0];
    float best = NEGV; int arg = 0;
    for (int j=0;j<Nk;j++){
        int inst = g_kidx[j];
        float v = g_sk[j] * (1.f/(1.f+expf(-pm[(size_t)inst*HWPX+p])));
        if (v > best){ best=v; arg=j; }
    }
    g_mids[p]=arg;
}

__global__ void k_areas(const float* __restrict__ pm){
    int j = blockIdx.x;
    if (j >= g_ints[0]) return;
    int inst = g_kidx[j];
    int cm=0,cp=0,ci=0;
    for (int p=threadIdx.x; p<HWPX; p+=256){
        int mm = (g_mids[p]==j);
        int pb = (pm[(size_t)inst*HWPX+p] >= 0.f);
        cm+=mm; cp+=pb; ci+=(mm&&pb);
    }
    __shared__ int r0[256],r1[256],r2[256];
    int t=threadIdx.x; r0[t]=cm; r1[t]=cp; r2[t]=ci; __syncthreads();
    for (int off=128; off>0; off>>=1){
        if (t<off){ r0[t]+=r0[t+off]; r1[t]+=r1[t+off]; r2[t]+=r2[t+off]; }
        __syncthreads();
    }
    if (t==0){ g_marea[j]=r0[0]; g_parea[j]=r1[0]; g_inter[j]=r2[0]; }
}

__global__ void k_select(){
    if (threadIdx.x | blockIdx.x) return;
    int Nk=g_ints[0], ns=0;
    for (int j=0;j<Nk;j++){
        if (g_inter[j] > 0 && ((float)g_marea[j]/(float)g_parea[j]) >= 0.8f){
            g_selj[ns]=j; g_k2idx[ns]=g_kidx[j]; ns++;
        }
    }
    g_ints[1]=ns;
}

__global__ void k_xyz(const float* __restrict__ pm){
    int s = blockIdx.x;
    if (s >= g_ints[1]) return;
    int j = g_selj[s], inst = g_k2idx[s];
    float sx=0,sy=0,sz=0;
    for (int p=threadIdx.x;p<HWPX;p+=256){
        if (g_mids[p]==j && pm[(size_t)inst*HWPX+p] >= 0.f){
            sx+=g_wx[p]; sy+=g_wy[p]; sz+=g_wz[p];
        }
    }
    __shared__ float r0[256],r1[256],r2[256];
    int t=threadIdx.x; r0[t]=sx; r1[t]=sy; r2[t]=sz; __syncthreads();
    for (int off=128; off>0; off>>=1){
        if (t<off){ r0[t]+=r0[t+off]; r1[t]+=r1[t+off]; r2[t]+=r2[t+off]; }
        __syncthreads();
    }
    if (t==0){ g_xyz[s*3+0]=r0[0]; g_xyz[s*3+1]=r1[0]; g_xyz[s*3+2]=r2[0]; }
}

__global__ void k_instbuild(const float* __restrict__ queries,
                            const float* __restrict__ instposw,
                            const float* __restrict__ posw){
    int s = blockIdx.x;
    if (s >= g_ints[1]) return;
    int c = threadIdx.x;
    int inst = g_k2idx[s];
    float x=g_xyz[s*3+0], y=g_xyz[s*3+1], z=g_xyz[s*3+2];
    gi_q[s*EMB+c] = queries[inst*EMB+c];
    gi_p[s*EMB+c] = instposw[inst*EMB+c] + posw[c*3+0]*x + posw[c*3+1]*y + posw[c*3+2]*z;
}

// ---------------- bf16x2-split tensor-core GEMM core ----------------
__device__ __forceinline__ void bsplit2(float x0, float x1, unsigned &hi, unsigned &lo){
    __nv_bfloat16 h0 = __float2bfloat16(x0);
    __nv_bfloat16 h1 = __float2bfloat16(x1);
    __nv_bfloat16 l0 = __float2bfloat16(x0 - __bfloat162float(h0));
    __nv_bfloat16 l1 = __float2bfloat16(x1 - __bfloat162float(h1));
    unsigned short uh0 = *reinterpret_cast<unsigned short*>(&h0);
    unsigned short uh1 = *reinterpret_cast<unsigned short*>(&h1);
    unsigned short ul0 = *reinterpret_cast<unsigned short*>(&l0);
    unsigned short ul1 = *reinterpret_cast<unsigned short*>(&l1);
    hi = (unsigned)uh0 | ((unsigned)uh1 << 16);
    lo = (unsigned)ul0 | ((unsigned)ul1 << 16);
}
#define MMA_BF16(d0,d1,d2,d3,a0,a1,a2,a3,b0,b1) \
  asm volatile("mma.sync.aligned.m16n8k16.row.col.f32.bf16.bf16.f32 " \
    "{%0,%1,%2,%3},{%4,%5,%6,%7},{%8,%9},{%0,%1,%2,%3};" \
    : "+f"(d0),"+f"(d1),"+f"(d2),"+f"(d3) \
    : "r"(a0),"r"(a1),"r"(a2),"r"(a3),"r"(b0),"r"(b1))

#define SMS 136

// store SRC[8] (K offsets KQ..KQ+7, row ROW) as split bf16x2 pairs
#define STORE_SPLIT_RC(SRC, ARR_H, ARR_L, ROW, KQ) do { \
    int kq2_ = (KQ) >> 1; \
    _Pragma("unroll") \
    for (int jj=0;jj<4;jj++){ \
        unsigned hv, lv; \
        bsplit2(SRC[2*jj], SRC[2*jj+1], hv, lv); \
        ARR_H[kq2_+jj][ROW] = hv; \
        ARR_L[kq2_+jj][ROW] = lv; \
    } \
} while(0)
#define STORE_SPLIT(SRC, ARR_H, ARR_L) STORE_SPLIT_RC(SRC, ARR_H, ARR_L, row_l, kq)

#define LOAD_FRAGS_AND_MMA() do { \
    unsigned ah[2][4], al[2][4]; \
    _Pragma("unroll") \
    for (int mt=0;mt<2;mt++){ \
        int r0 = mb + mt*16 + g; \
        ah[mt][0]=Ah[t][r0];   ah[mt][1]=Ah[t][r0+8]; \
        ah[mt][2]=Ah[t+4][r0]; ah[mt][3]=Ah[t+4][r0+8]; \
        al[mt][0]=Al[t][r0];   al[mt][1]=Al[t][r0+8]; \
        al[mt][2]=Al[t+4][r0]; al[mt][3]=Al[t+4][r0+8]; \
    } \
    _Pragma("unroll") \
    for (int j=0;j<8;j++){ \
        int nc = nb + j*8 + g; \
        unsigned bh0=Wh[t][nc], bh1=Wh[t+4][nc]; \
        unsigned bl0=Wl[t][nc], bl1=Wl[t+4][nc]; \
        _Pragma("unroll") \
        for (int mt=0;mt<2;mt++){ \
            MMA_BF16(acc[mt][j][0],acc[mt][j][1],acc[mt][j][2],acc[mt][j][3], \
                     al[mt][0],al[mt][1],al[mt][2],al[mt][3], bh0,bh1); \
            MMA_BF16(acc[mt][j][0],acc[mt][j][1],acc[mt][j][2],acc[mt][j][3], \
                     ah[mt][0],ah[mt][1],ah[mt][2],ah[mt][3], bl0,bl1); \
            MMA_BF16(acc[mt][j][0],acc[mt][j][1],acc[mt][j][2],acc[mt][j][3], \
                     ah[mt][0],ah[mt][1],ah[mt][2],ah[mt][3], bh0,bh1); \
        } \
    } \
} while(0)

// 64-N variant: j loops 4
#define LOAD_FRAGS_AND_MMA_N64() do { \
    unsigned ah[2][4], al[2][4]; \
    _Pragma("unroll") \
    for (int mt=0;mt<2;mt++){ \
        int r0 = mb + mt*16 + g; \
        ah[mt][0]=Ah[t][r0];   ah[mt][1]=Ah[t][r0+8]; \
        ah[mt][2]=Ah[t+4][r0]; ah[mt][3]=Ah[t+4][r0+8]; \
        al[mt][0]=Al[t][r0];   al[mt][1]=Al[t][r0+8]; \
        al[mt][2]=Al[t+4][r0]; al[mt][3]=Al[t+4][r0+8]; \
    } \
    _Pragma("unroll") \
    for (int j=0;j<4;j++){ \
        int nc = nb + j*8 + g; \
        unsigned bh0=Wh[t][nc], bh1=Wh[t+4][nc]; \
        unsigned bl0=Wl[t][nc], bl1=Wl[t+4][nc]; \
        _Pragma("unroll") \
        for (int mt=0;mt<2;mt++){ \
            MMA_BF16(acc[mt][j][0],acc[mt][j][1],acc[mt][j][2],acc[mt][j][3], \
                     al[mt][0],al[mt][1],al[mt][2],al[mt][3], bh0,bh1); \
            MMA_BF16(acc[mt][j][0],acc[mt][j][1],acc[mt][j][2],acc[mt][j][3], \
                     ah[mt][0],ah[mt][1],ah[mt][2],ah[mt][3], bl0,bl1); \
            MMA_BF16(acc[mt][j][0],acc[mt][j][1],acc[mt][j][2],acc[mt][j][3], \
                     ah[mt][0],ah[mt][1],ah[mt][2],ah[mt][3], bh0,bh1); \
        } \
    } \
} while(0)

// Generic GEMM, 128M x 64N tiles, 3 CTA/SM target.
// C = (A (+A2 if bn<a2lim)) @ W^T + bias, opt relu, dual out.
__global__ void __launch_bounds__(256,3) k_gemm(
    const float* __restrict__ A, const float* __restrict__ A2, int a2lim,
    const float* __restrict__ W, const float* __restrict__ bias,
    float* __restrict__ C0, float* __restrict__ C1,
    int N, int K, int relu, int cstride)
{
    __shared__ unsigned Ah[8][SMS], Al[8][SMS], Wh[8][72], Wl[8][72];
    int M = g_ints[2];
    int bn = blockIdx.x * 64;
    const float* A2u = (A2 && bn < a2lim) ? A2 : NULL;
    int tid = threadIdx.x;
    int row_l = tid & 127;
    int kq    = (tid >> 7) * 8;
    int row_w = tid & 63;
    int kqw   = ((tid >> 6) & 1) * 8;
    int w = tid >> 5, lane = tid & 31;
    int g = lane >> 2, t = lane & 3;
    int mb = (w >> 1) * 32, nb = (w & 1) * 32;

    for (int bm = blockIdx.y*128; bm < M; bm += gridDim.y*128){
        float acc[2][4][4];
        #pragma unroll
        for (int mt=0;mt<2;mt++)
            #pragma unroll
            for (int j=0;j<4;j++)
                #pragma unroll
                for (int q=0;q<4;q++) acc[mt][j][q]=0.f;

        for (int kt=0; kt<K; kt+=16){
            {
                int arow = bm + row_l;
                float va[8];
                if (arow < M){
                    const float* pa = &A[(size_t)arow*K + kt + kq];
                    float4 v0 = *(const float4*)pa, v1 = *(const float4*)(pa+4);
                    va[0]=v0.x; va[1]=v0.y; va[2]=v0.z; va[3]=v0.w;
                    va[4]=v1.x; va[5]=v1.y; va[6]=v1.z; va[7]=v1.w;
                    if (A2u){
                        const float* pb = &A2u[(size_t)arow*K + kt + kq];
                        float4 u0 = *(const float4*)pb, u1 = *(const float4*)(pb+4);
                        va[0]+=u0.x; va[1]+=u0.y; va[2]+=u0.z; va[3]+=u0.w;
                        va[4]+=u1.x; va[5]+=u1.y; va[6]+=u1.z; va[7]+=u1.w;
                    }
                } else {
                    #pragma unroll
                    for (int j=0;j<8;j++) va[j]=0.f;
                }
                STORE_SPLIT(va, Ah, Al);
                if (tid < 128){
                    const float* pw = &W[(size_t)(bn+row_w)*K + kt + kqw];
                    float4 w0 = *(const float4*)pw, w1 = *(const float4*)(pw+4);
                    float vw[8] = {w0.x,w0.y,w0.z,w0.w,w1.x,w1.y,w1.z,w1.w};
                    STORE_SPLIT_RC(vw, Wh, Wl, row_w, kqw);
                }
            }
            __syncthreads();
            LOAD_FRAGS_AND_MMA_N64();
            __syncthreads();
        }
        #pragma unroll
        for (int mt=0;mt<2;mt++){
            #pragma unroll
            for (int j=0;j<4;j++){
                int col = bn + nb + j*8 + t*2;
                float b0v = bias[col], b1v = bias[col+1];
                float* Cd = C0; int cc = col;
                if (C1 && col >= 128){ Cd = C1; cc = col - 128; }
                int r0 = bm + mb + mt*16 + g;
                if (r0 < M){
                    float v0 = acc[mt][j][0] + b0v;
                    float v1 = acc[mt][j][1] + b1v;
                    if (relu){ v0=fmaxf(v0,0.f); v1=fmaxf(v1,0.f); }
                    *(float2*)&Cd[(size_t)r0*cstride + cc] = make_float2(v0,v1);
                }
                int r1 = r0 + 8;
                if (r1 < M){
                    float v0 = acc[mt][j][2] + b0v;
                    float v1 = acc[mt][j][3] + b1v;
                    if (relu){ v0=fmaxf(v0,0.f); v1=fmaxf(v1,0.f); }
                    *(float2*)&Cd[(size_t)r1*cstride + cc] = make_float2(v0,v1);
                }
            }
        }
    }
}

// GEMM (N=128) + bias + residual(s) + LayerNorm fused epilogue (128-wide tiles).
__global__ void __launch_bounds__(256,2) k_gemm_ln(
    const float* __restrict__ A, const float* __restrict__ W,
    const float* __restrict__ bias,
    const float* __restrict__ res1, const float* __restrict__ res2,
    const float* __restrict__ gam, const float* __restrict__ bet,
    float* __restrict__ C, int K)
{
    __shared__ unsigned Ah[8][SMS], Al[8][SMS], Wh[8][SMS], Wl[8][SMS];
    __shared__ float ssum[128][2], ssq[128][2];
    int M = g_ints[2];
    int tid = threadIdx.x;
    int row_l = tid & 127;
    int kq    = (tid >> 7) * 8;
    int w = tid >> 5, lane = tid & 31;
    int g = lane >> 2, t = lane & 3;
    int mb = (w >> 1) * 32, nb = (w & 1) * 64;

    for (int bm = blockIdx.y*128; bm < M; bm += gridDim.y*128){
        float acc[2][8][4];
        #pragma unroll
        for (int mt=0;mt<2;mt++)
            #pragma unroll
            for (int j=0;j<8;j++)
                #pragma unroll
                for (int q=0;q<4;q++) acc[mt][j][q]=0.f;

        for (int kt=0; kt<K; kt+=16){
            {
                int arow = bm + row_l;
                float va[8];
                if (arow < M){
                    const float* pa = &A[(size_t)arow*K + kt + kq];
                    float4 v0 = *(const float4*)pa, v1 = *(const float4*)(pa+4);
                    va[0]=v0.x; va[1]=v0.y; va[2]=v0.z; va[3]=v0.w;
                    va[4]=v1.x; va[5]=v1.y; va[6]=v1.z; va[7]=v1.w;
                } else {
                    #pragma unroll
                    for (int j=0;j<8;j++) va[j]=0.f;
                }
                STORE_SPLIT(va, Ah, Al);
                const float* pw = &W[(size_t)row_l*K + kt + kq];
                float4 w0 = *(const float4*)pw, w1 = *(const float4*)(pw+4);
                float vw[8] = {w0.x,w0.y,w0.z,w0.w,w1.x,w1.y,w1.z,w1.w};
                STORE_SPLIT(vw, Wh, Wl);
            }
            __syncthreads();
            LOAD_FRAGS_AND_MMA();
            __syncthreads();
        }
        #pragma unroll
        for (int mt=0;mt<2;mt++){
            #pragma unroll
            for (int j=0;j<8;j++){
                int col = nb + j*8 + t*2;
                float b0v = bias[col], b1v = bias[col+1];
                int r0 = bm + mb + mt*16 + g, r1 = r0 + 8;
                size_t o0 = (size_t)r0*EMB + col, o1 = (size_t)r1*EMB + col;
                float a0 = acc[mt][j][0] + b0v + res1[o0];
                float a1 = acc[mt][j][1] + b1v + res1[o0+1];
                float a2 = acc[mt][j][2] + b0v + res1[o1];
                float a3 = acc[mt][j][3] + b1v + res1[o1+1];
                if (res2){
                    a0 += res2[o0]; a1 += res2[o0+1];
                    a2 += res2[o1]; a3 += res2[o1+1];
                }
                acc[mt][j][0]=a0; acc[mt][j][1]=a1; acc[mt][j][2]=a2; acc[mt][j][3]=a3;
            }
        }
        float s_[2][2], q_[2][2];
        #pragma unroll
        for (int mt=0;mt<2;mt++){
            s_[mt][0]=0.f; s_[mt][1]=0.f; q_[mt][0]=0.f; q_[mt][1]=0.f;
            #pragma unroll
            for (int j=0;j<8;j++){
                s_[mt][0]+=acc[mt][j][0]+acc[mt][j][1];
                q_[mt][0]+=acc[mt][j][0]*acc[mt][j][0]+acc[mt][j][1]*acc[mt][j][1];
                s_[mt][1]+=acc[mt][j][2]+acc[mt][j][3];
                q_[mt][1]+=acc[mt][j][2]*acc[mt][j][2]+acc[mt][j][3]*acc[mt][j][3];
            }
        }
        #pragma unroll
        for (int off=1; off<4; off<<=1){
            #pragma unroll
            for (int mt=0;mt<2;mt++){
                s_[mt][0]+=__shfl_xor_sync(0xffffffffu, s_[mt][0], off);
                s_[mt][1]+=__shfl_xor_sync(0xffffffffu, s_[mt][1], off);
                q_[mt][0]+=__shfl_xor_sync(0xffffffffu, q_[mt][0], off);
                q_[mt][1]+=__shfl_xor_sync(0xffffffffu, q_[mt][1], off);
            }
        }
        if (t == 0){
            #pragma unroll
            for (int mt=0;mt<2;mt++){
                int rA = mb + mt*16 + g, rB = rA + 8;
                ssum[rA][w&1]=s_[mt][0]; ssq[rA][w&1]=q_[mt][0];
                ssum[rB][w&1]=s_[mt][1]; ssq[rB][w&1]=q_[mt][1];
            }
        }
        __syncthreads();
        #pragma unroll
        for (int mt=0;mt<2;mt++){
            int rA = mb + mt*16 + g, rB = rA + 8;
            float su0 = ssum[rA][0]+ssum[rA][1], sq0 = ssq[rA][0]+ssq[rA][1];
            float su1 = ssum[rB][0]+ssum[rB][1], sq1 = ssq[rB][0]+ssq[rB][1];
            float mu0 = su0/128.f, mu1 = su1/128.f;
            float rs0 = rsqrtf(sq0/128.f - mu0*mu0 + 1e-5f);
            float rs1 = rsqrtf(sq1/128.f - mu1*mu1 + 1e-5f);
            int r0 = bm + rA, r1 = bm + rB;
            #pragma unroll
            for (int j=0;j<8;j++){
                int col = nb + j*8 + t*2;
                float g0 = gam[col], g1 = gam[col+1];
                float e0 = bet[col], e1 = bet[col+1];
                if (r0 < M){
                    float v0 = (acc[mt][j][0]-mu0)*rs0*g0+e0;
                    float v1 = (acc[mt][j][1]-mu0)*rs0*g1+e1;
                    *(float2*)&C[(size_t)r0*EMB + col] = make_float2(v0,v1);
                }
                if (r1 < M){
                    float v0 = (acc[mt][j][2]-mu1)*rs1*g0+e0;
                    float v1 = (acc[mt][j][3]-mu1)*rs1*g1+e1;
                    *(float2*)&C[(size_t)r1*EMB + col] = make_float2(v0,v1);
                }
            }
        }
        __syncthreads();
    }
}

// ---------------- fused branch-1 attention megakernel ----------------
#define B1A_AH   0
#define B1A_AL   4352
#define B1A_WH   8704
#define B1A_WL   13056
#define B1A_SQ   17408
#define B1A_SO   (17408 + 67584)
#define B1A_SSUM (17408 + 135168)
#define B1A_SSQ  (17408 + 135168 + 1024)
#define B1_SMEM  (17408 + 135168 + 2048)
__global__ void __launch_bounds__(256) k_b1attn(
    const float* __restrict__ se, const float* __restrict__ sp,
    const float* __restrict__ Wq, const float* __restrict__ bq,
    const float* __restrict__ Wo, const float* __restrict__ bo,
    const float* __restrict__ gam, const float* __restrict__ bet,
    float* __restrict__ X)
{
    extern __shared__ unsigned char dsm[];
    unsigned (*Ah)[SMS] = (unsigned (*)[SMS])(dsm + B1A_AH);
    unsigned (*Al)[SMS] = (unsigned (*)[SMS])(dsm + B1A_AL);
    unsigned (*Wh)[SMS] = (unsigned (*)[SMS])(dsm + B1A_WH);
    unsigned (*Wl)[SMS] = (unsigned (*)[SMS])(dsm + B1A_WL);
    float (*sQ)[132]    = (float (*)[132])(dsm + B1A_SQ);
    float (*sO)[132]    = (float (*)[132])(dsm + B1A_SO);
    float (*ssum)[2]    = (float (*)[2])(dsm + B1A_SSUM);
    float (*ssq)[2]     = (float (*)[2])(dsm + B1A_SSQ);

    int M = g_ints[2];
    int Ns = g_ints[1];
    int tid = threadIdx.x;
    int row_l = tid & 127;
    int kq    = (tid >> 7) * 8;
    int w = tid >> 5, lane = tid & 31;
    int g = lane >> 2, t = lane & 3;
    int mb = (w >> 1) * 32, nb = (w & 1) * 64;

    for (int bm = blockIdx.y*128; bm < M; bm += gridDim.y*128){
        float acc[2][8][4];
        #pragma unroll
        for (int mt=0;mt<2;mt++)
            #pragma unroll
            for (int j=0;j<8;j++)
                #pragma unroll
                for (int q=0;q<4;q++) acc[mt][j][q]=0.f;

        for (int kt=0; kt<EMB; kt+=16){
            {
                int arow = bm + row_l;
                float va[8];
                if (arow < M){
                    const float* pa = &se[(size_t)arow*EMB + kt + kq];
                    const float* pb = &sp[(size_t)arow*EMB + kt + kq];
                    float4 v0 = *(const float4*)pa, v1 = *(const float4*)(pa+4);
                    float4 u0 = *(const float4*)pb, u1 = *(const float4*)(pb+4);
                    va[0]=v0.x+u0.x; va[1]=v0.y+u0.y; va[2]=v0.z+u0.z; va[3]=v0.w+u0.w;
                    va[4]=v1.x+u1.x; va[5]=v1.y+u1.y; va[6]=v1.z+u1.z; va[7]=v1.w+u1.w;
                } else {
                    #pragma unroll
                    for (int j=0;j<8;j++) va[j]=0.f;
                }
                STORE_SPLIT(va, Ah, Al);
                const float* pw = &Wq[(size_t)row_l*EMB + kt + kq];
                float4 w0 = *(const float4*)pw, w1 = *(const float4*)(pw+4);
                float vw[8] = {w0.x,w0.y,w0.z,w0.w,w1.x,w1.y,w1.z,w1.w};
                STORE_SPLIT(vw, Wh, Wl);
            }
            __syncthreads();
            LOAD_FRAGS_AND_MMA();
            __syncthreads();
        }
        #pragma unroll
        for (int mt=0;mt<2;mt++){
            #pragma unroll
            for (int j=0;j<8;j++){
                int col = nb + j*8 + t*2;
                int ph = ((col>>5)*33) + (col&31);
                float b0v = bq[col], b1v = bq[col+1];
                int rA = mb + mt*16 + g, rB = rA + 8;
                sQ[rA][ph]   = acc[mt][j][0] + b0v;
                sQ[rA][ph+1] = acc[mt][j][1] + b1v;
                sQ[rB][ph]   = acc[mt][j][2] + b0v;
                sQ[rB][ph+1] = acc[mt][j][3] + b1v;
            }
        }
        __syncthreads();

        #pragma unroll
        for (int half=0; half<2; half++){
            int row = half*64 + (tid>>2);
            int h = tid & 3;
            int pb = h*33;
            float m = NEGV, l = 0.f, pacc[32];
            #pragma unroll
            for (int d=0;d<32;d++) pacc[d]=0.f;
            for (int j=0;j<Ns;j++){
                const float* kr = &gi_Kp[j*EMB + h*32];
                float dsum = 0.f;
                #pragma unroll
                for (int d=0;d<32;d++) dsum += sQ[row][pb+d]*kr[d];
                dsum *= 0.17677669529663687f;
                float nm = fmaxf(m, dsum);
                float fac = expf(m-nm), e = expf(dsum-nm);
                l = l*fac + e;
                const float* vr = &gi_Vp[j*EMB + h*32];
                #pragma unroll
                for (int d=0;d<32;d++) pacc[d] = pacc[d]*fac + e*vr[d];
                m = nm;
            }
            float inv = 1.f/l;
            #pragma unroll
            for (int d=0;d<32;d++) sO[row][h*32+d] = pacc[d]*inv;
        }
        __syncthreads();

        #pragma unroll
        for (int mt=0;mt<2;mt++)
            #pragma unroll
            for (int j=0;j<8;j++)
                #pragma unroll
                for (int q=0;q<4;q++) acc[mt][j][q]=0.f;

        for (int kt=0; kt<EMB; kt+=16){
            {
                float va[8];
                #pragma unroll
                for (int j=0;j<8;j++) va[j] = sO[row_l][kt+kq+j];
                STORE_SPLIT(va, Ah, Al);
                const float* pw = &Wo[(size_t)row_l*EMB + kt + kq];
                float4 w0 = *(const float4*)pw, w1 = *(const float4*)(pw+4);
                float vw[8] = {w0.x,w0.y,w0.z,w0.w,w1.x,w1.y,w1.z,w1.w};
                STORE_SPLIT(vw, Wh, Wl);
            }
            __syncthreads();
            LOAD_FRAGS_AND_MMA();
            __syncthreads();
        }
        #pragma unroll
        for (int mt=0;mt<2;mt++){
            #pragma unroll
            for (int j=0;j<8;j++){
                int col = nb + j*8 + t*2;
                float b0v = bo[col], b1v = bo[col+1];
                int r0 = bm + mb + mt*16 + g, r1 = r0 + 8;
                size_t o0 = (size_t)min(r0, M-1)*EMB + col;
                size_t o1 = (size_t)min(r1, M-1)*EMB + col;
                float a0 = acc[mt][j][0] + b0v + se[o0] + sp[o0];
                float a1 = acc[mt][j][1] + b1v + se[o0+1] + sp[o0+1];
                float a2 = acc[mt][j][2] + b0v + se[o1] + sp[o1];
                float a3 = acc[mt][j][3] + b1v + se[o1+1] + sp[o1+1];
                acc[mt][j][0]=a0; acc[mt][j][1]=a1; acc[mt][j][2]=a2; acc[mt][j][3]=a3;
            }
        }
        float s_[2][2], q_[2][2];
        #pragma unroll
        for (int mt=0;mt<2;mt++){
            s_[mt][0]=0.f; s_[mt][1]=0.f; q_[mt][0]=0.f; q_[mt][1]=0.f;
            #pragma unroll
            for (int j=0;j<8;j++){
                s_[mt][0]+=acc[mt][j][0]+acc[mt][j][1];
                q_[mt][0]+=acc[mt][j][0]*acc[mt][j][0]+acc[mt][j][1]*acc[mt][j][1];
                s_[mt][1]+=acc[mt][j][2]+acc[mt][j][3];
                q_[mt][1]+=acc[mt][j][2]*acc[mt][j][2]+acc[mt][j][3]*acc[mt][j][3];
            }
        }
        #pragma unroll
        for (int off=1; off<4; off<<=1){
            #pragma unroll
            for (int mt=0;mt<2;mt++){
                s_[mt][0]+=__shfl_xor_sync(0xffffffffu, s_[mt][0], off);
                s_[mt][1]+=__shfl_xor_sync(0xffffffffu, s_[mt][1], off);
                q_[mt][0]+=__shfl_xor_sync(0xffffffffu, q_[mt][0], off);
                q_[mt][1]+=__shfl_xor_sync(0xffffffffu, q_[mt][1], off);
            }
        }
        if (t == 0){
            #pragma unroll
            for (int mt=0;mt<2;mt++){
                int rA = mb + mt*16 + g, rB = rA + 8;
                ssum[rA][w&1]=s_[mt][0]; ssq[rA][w&1]=q_[mt][0];
                ssum[rB][w&1]=s_[mt][1]; ssq[rB][w&1]=q_[mt][1];
            }
        }
        __syncthreads();
        #pragma unroll
        for (int mt=0;mt<2;mt++){
            int rA = mb + mt*16 + g, rB = rA + 8;
            float su0 = ssum[rA][0]+ssum[rA][1], sq0 = ssq[rA][0]+ssq[rA][1];
            float su1 = ssum[rB][0]+ssum[rB][1], sq1 = ssq[rB][0]+ssq[rB][1];
            float mu0 = su0/128.f, mu1 = su1/128.f;
            float rs0 = rsqrtf(sq0/128.f - mu0*mu0 + 1e-5f);
            float rs1 = rsqrtf(sq1/128.f - mu1*mu1 + 1e-5f);
            int r0 = bm + rA, r1 = bm + rB;
            #pragma unroll
            for (int j=0;j<8;j++){
                int col = nb + j*8 + t*2;
                float g0 = gam[col], g1 = gam[col+1];
                float e0 = bet[col], e1 = bet[col+1];
                if (r0 < M){
                    float v0 = (acc[mt][j][0]-mu0)*rs0*g0+e0;
                    float v1 = (acc[mt][j][1]-mu0)*rs0*g1+e1;
                    *(float2*)&X[(size_t)r0*EMB + col] = make_float2(v0,v1);
                }
                if (r1 < M){
                    float v0 = (acc[mt][j][2]-mu1)*rs1*g0+e0;
                    float v1 = (acc[mt][j][3]-mu1)*rs1*g1+e1;
                    *(float2*)&X[(size_t)r1*EMB + col] = make_float2(v0,v1);
                }
            }
        }
        __syncthreads();
    }
}

// ---------------- fused instance-side kernels ----------------
__device__ __forceinline__ float block_ln(float x, float* red, int t,
                                          const float* g, const float* b){
    red[t]=x; __syncthreads();
    for (int off=64; off>0; off>>=1){ if (t<off) red[t]+=red[t+off]; __syncthreads(); }
    float mu = red[0]/128.f; __syncthreads();
    float d = x-mu;
    red[t]=d*d; __syncthreads();
    for (int off=64; off>0; off>>=1){ if (t<off) red[t]+=red[t+off]; __syncthreads(); }
    float var = red[0]/128.f; __syncthreads();
    return d*rsqrtf(var+1e-5f)*g[t]+b[t];
}

__global__ void k_inst_pre(const float* __restrict__ wq, const float* __restrict__ bq){
    int s = blockIdx.x;
    if (s >= g_ints[1]) return;
    int c = threadIdx.x;
    __shared__ float sq_[EMB];
    float qin = gi_q[s*EMB+c] + gi_p[s*EMB+c];
    gi_qin[s*EMB+c] = qin;
    sq_[c] = qin; __syncthreads();
    float acc = bq[c];
    const float* wr = &wq[c*EMB];
    #pragma unroll 8
    for (int k=0;k<EMB;k++) acc += sq_[k]*wr[k];
    gi_Qp[s*EMB+c] = acc;
}

__global__ void k_inst_kv(const float* __restrict__ wk, const float* __restrict__ bk,
                          const float* __restrict__ wv, const float* __restrict__ bv){
    int s = blockIdx.x;
    if (s >= g_ints[1]) return;
    int c = threadIdx.x;
    __shared__ float sqin[EMB], sq_[EMB];
    float qv = gi_q[s*EMB+c];
    sqin[c] = qv + gi_p[s*EMB+c];
    sq_[c]  = qv;
    __syncthreads();
    float ak = bk[c], av = bv[c];
    const float* wkr = &wk[c*EMB];
    const float* wvr = &wv[c*EMB];
    #pragma unroll 8
    for (int k=0;k<EMB;k++){ ak += sqin[k]*wkr[k]; av += sq_[k]*wvr[k]; }
    gi_Kp[s*EMB+c] = ak;
    gi_Vp[s*EMB+c] = av;
}

__global__ void k_inst_post(const float* __restrict__ wo, const float* __restrict__ bo,
                            const float* __restrict__ lg, const float* __restrict__ lb,
                            const float* __restrict__ w1, const float* __restrict__ b1,
                            const float* __restrict__ w2, const float* __restrict__ b2){
    int s = blockIdx.x;
    if (s >= g_ints[1]) return;
    int c = threadIdx.x;
    __shared__ float sO[EMB], sx[EMB], sh[HIDN], red[EMB];
    {
        int h = c>>5, lane = c&31;
        float m = NEGV, l = 0.f, a = 0.f;
        int base = (h*NIM + s)*16;
        for (int ck=0;ck<16;ck++){
            float mc = g_pm[base+ck], lc = g_pl[base+ck];
            float ac = g_pacc[(size_t)(base+ck)*32 + lane];
            float nm = fmaxf(m, mc);
            float fa = expf(m-nm), fb = expf(mc-nm);
            l = l*fa + lc*fb;
            a = a*fa + ac*fb;
            m = nm;
        }
        sO[c] = a/l;
    }
    __syncthreads();
    float mha = bo[c];
    {
        const float* wr = &wo[c*EMB];
        #pragma unroll 8
        for (int k=0;k<EMB;k++) mha += sO[k]*wr[k];
    }
    float x = block_ln(gi_qin[s*EMB+c] + mha, red, c, lg, lb);
    sx[c] = x; __syncthreads();
    #pragma unroll
    for (int hc=c; hc<HIDN; hc+=EMB){
        float a = b1[hc];
        const float* wr = &w1[hc*EMB];
        #pragma unroll 8
        for (int k=0;k<EMB;k++) a += sx[k]*wr[k];
        sh[hc] = fmaxf(a, 0.f);
    }
    __syncthreads();
    float h2 = b2[c];
    {
        const float* wr = &w2[c*HIDN];
        #pragma unroll 8
        for (int k=0;k<HIDN;k++) h2 += sh[k]*wr[k];
    }
    gi_q[s*EMB+c] = block_ln(x + h2, red, c, lg+EMB, lb+EMB);
}

// ---------------- attn0: 8 instances per block, smem-staged K/V ----------------
__global__ void __launch_bounds__(256) k_attn0p(
    const float* __restrict__ Kp, const float* __restrict__ Vp)
{
    int Ns = g_ints[1];
    int grp = blockIdx.z;
    if (grp*8 >= Ns) return;
    int h = blockIdx.y;
    int c = blockIdx.x;           // 0..15
    int Nf = g_ints[2];
    int chunk = (Nf + 15) >> 4;
    int k0 = c*chunk, k1 = min(k0+chunk, Nf);
    int tid = threadIdx.x;
    int is = tid >> 5, kl = tid & 31;
    int s = grp*8 + is;
    bool sok = (s < Ns);

    __shared__ float sK[32][33], sV[32][33];
    __shared__ float sq[8][33];
    if (sok) sq[is][kl] = gi_Qp[s*EMB + h*32 + kl] * 0.17677669529663687f;
    __syncthreads();

    float m = NEGV, l = 0.f, acc[32];
    #pragma unroll
    for (int d=0;d<32;d++) acc[d]=0.f;

    for (int kp0 = k0; kp0 < k1; kp0 += 32){
        int nk = min(32, k1 - kp0);
        for (int idx = tid; idx < nk*32; idx += 256){
            int kr = idx >> 5, d = idx & 31;
            sK[kr][d] = Kp[(size_t)(kp0+kr)*EMB + h*32 + d];
            sV[kr][d] = Vp[(size_t)(kp0+kr)*EMB + h*32 + d];
        }
        __syncthreads();
        if (sok && kl < nk){
            float dsum = 0.f;
            #pragma unroll
            for (int d=0;d<32;d++) dsum += sq[is][d]*sK[kl][d];
            float nm = fmaxf(m, dsum);
            float fac = expf(m - nm);
            float e = expf(dsum - nm);
            l = l*fac + e;
            #pragma unroll
            for (int d=0;d<32;d++) acc[d] = acc[d]*fac + e*sV[kl][d];
            m = nm;
        }
        __syncthreads();
    }

    #pragma unroll
    for (int off=16; off>0; off>>=1){
        float mo = __shfl_xor_sync(0xffffffffu, m, off);
        float lo = __shfl_xor_sync(0xffffffffu, l, off);
        float nm = fmaxf(m, mo);
        float fa = expf(m-nm), fb = expf(mo-nm);
        l = l*fa + lo*fb;
        #pragma unroll
        for (int d=0;d<32;d++){
            float ao = __shfl_xor_sync(0xffffffffu, acc[d], off);
            acc[d] = acc[d]*fa + ao*fb;
        }
        m = nm;
    }

    if (sok){
        int pi = (h*NIM + s)*16 + c;
        if (kl == 0){ g_pm[pi] = m; g_pl[pi] = l; }
        #pragma unroll
        for (int d=0;d<32;d++)
            if (kl == d) g_pacc[(size_t)pi*32 + d] = acc[d];
    }
}

// ---------------- final conv (with inline scatter of se) ----------------
__global__ void __launch_bounds__(256) k_conv(
    const void* __restrict__ fm,
    const float* __restrict__ cw, const float* __restrict__ cb,
    float* __restrict__ out)
{
    __shared__ float scw[20*EMB];
    __shared__ float scb[20];
    for (int i=threadIdx.x; i<20*EMB; i+=256) scw[i]=cw[i];
    if (threadIdx.x < 20) scb[threadIdx.x]=cb[threadIdx.x];
    __syncthreads();
    int n = blockIdx.x*256 + threadIdx.x;
    const float* row;
    if (fov_get(fm, n)) row = &g_se[(size_t)g_inv[n]*EMB];
    else                row = &g_full[(size_t)n*EMB];
    float r[EMB/4][4];
    #pragma unroll
    for (int k=0;k<EMB/4;k++) *(float4*)r[k] = *(const float4*)&row[k*4];
    for (int o=0;o<20;o++){
        float acc = scb[o];
        const float* w = &scw[o*EMB];
        #pragma unroll
        for (int k=0;k<EMB;k++) acc += r[k>>2][k&3]*w[k];
        out[(size_t)o*NQv + n] = acc;
    }
}

// ---------------- host ----------------
extern "C" void kernel_launch(void* const* d_in, const int* in_sizes, int n_in,
                              void* d_out, int out_size)
{
    const float* queries  = (const float*)d_in[0];
    const float* logits   = (const float*)d_in[1];
    const float* pmasks   = (const float*)d_in[2];
    const float* x3d      = (const float*)d_in[3];
    const float* depth    = (const float*)d_in[4];
    const float* Km       = (const float*)d_in[5];
    const float* Em       = (const float*)d_in[6];
    const float* vo       = (const float*)d_in[7];
    const void * fov      = (const void *)d_in[8];
    const float* sew      = (const float*)d_in[9];
    const float* instposw = (const float*)d_in[10];
    const float* posw     = (const float*)d_in[11];
    const float* convw    = (const float*)d_in[12];
    const float* convb    = (const float*)d_in[13];
    const float* attw     = (const float*)d_in[14];
    const float* attb     = (const float*)d_in[15];
    const float* lng      = (const float*)d_in[16];
    const float* lnb      = (const float*)d_in[17];
    const float* fw1      = (const float*)d_in[18];
    const float* fb1      = (const float*)d_in[19];
    const float* fw2      = (const float*)d_in[20];
    const float* fb2      = (const float*)d_in[21];
    float* out = (float*)d_out;

    float *p_se, *p_sp, *p_bA, *p_hid;
    cudaGetSymbolAddress((void**)&p_se,  g_se);
    cudaGetSymbolAddress((void**)&p_sp,  g_sp);
    cudaGetSymbolAddress((void**)&p_bA,  g_bA);
    cudaGetSymbolAddress((void**)&p_hid, g_hid);

    cudaFuncSetAttribute(k_b1attn, cudaFuncAttributeMaxDynamicSharedMemorySize, B1_SMEM);

    const size_t E2 = (size_t)EMB*EMB;

    // fov + scene setup
    k_fovdetect<<<1,256>>>((const unsigned int*)fov);
    k_fovcount<<<512,512>>>(fov);
    k_fovscan<<<1,512>>>();
    k_fovscatter<<<512,512>>>(fov);
    dim3 tb(32,8);
    k_buildfull<<<dim3(NQv/32,4),tb>>>(fov, sew, x3d, posw, vo);

    // instance post-processing
    k_world<<<(HWPX+255)/256,256>>>(depth, Km, Em);
    k_scores<<<1,320>>>(logits);
    k_mids<<<(HWPX+255)/256,256>>>(pmasks);
    k_areas<<<NIc,256>>>(pmasks);
    k_select<<<1,1>>>();
    k_xyz<<<NIc,256>>>(pmasks);
    k_instbuild<<<NIc,128>>>(queries, instposw, posw);

    for (int i=0;i<2;i++){
        // ---- branch 0: update inst queries (attend to scene) ----
        const float* aw = attw + (size_t)(i*2+0)*4*E2;
        const float* ab = attb + (size_t)(i*2+0)*4*EMB;
        const float* g0 = lng + (size_t)(i*2+0)*2*EMB;
        const float* b0 = lnb + (size_t)(i*2+0)*2*EMB;
        k_inst_pre<<<NIc,128>>>(aw+0*E2, ab+0*EMB);
        k_gemm<<<dim3(4,148),256>>>(p_se, p_sp, 128, aw+1*E2, ab+1*EMB,
                                    p_bA, p_hid, 256, EMB, 0, EMB);   // Kp->bA, Vp->hid
        k_attn0p<<<dim3(16,4,(NIc+7)/8),256>>>(p_bA, p_hid);
        k_inst_post<<<NIc,128>>>(aw+3*E2, ab+3*EMB, g0, b0,
                                 fw1+(size_t)(i*2+0)*HIDN*EMB, fb1+(size_t)(i*2+0)*HIDN,
                                 fw2+(size_t)(i*2+0)*EMB*HIDN, fb2+(size_t)(i*2+0)*EMB);

        // ---- branch 1: update scene embeddings (attend to inst) ----
        aw = attw + (size_t)(i*2+1)*4*E2;
        ab = attb + (size_t)(i*2+1)*4*EMB;
        const float* g1v = lng + (size_t)(i*2+1)*2*EMB;
        const float* b1v = lnb + (size_t)(i*2+1)*2*EMB;
        k_inst_kv<<<NIc,128>>>(aw+1*E2, ab+1*EMB, aw+2*E2, ab+2*EMB);
        k_b1attn<<<dim3(1,512),256,B1_SMEM>>>(p_se, p_sp,
                                              aw+0*E2, ab+0*EMB,
                                              aw+3*E2, ab+3*EMB,
                                              g1v, b1v, p_bA);        // x -> bA
        k_gemm<<<dim3(8,148),256>>>(p_bA, NULL, 0,
                                    fw1+(size_t)(i*2+1)*HIDN*EMB, fb1+(size_t)(i*2+1)*HIDN,
                                    p_hid, NULL, HIDN, EMB, 1, HIDN);
        k_gemm_ln<<<dim3(1,296),256>>>(p_hid,
                                       fw2+(size_t)(i*2+1)*EMB*HIDN, fb2+(size_t)(i*2+1)*EMB,
                                       p_bA, NULL, g1v+EMB, b1v+EMB, p_se, HIDN);
    }

    k_conv<<<NQv/256,256>>>(fov, convw, convb, out);
}

// round 14
// speedup vs baseline: 1.1029x; 1.1029x over previous
#include <cuda_runtime.h>
#include <cuda_bf16.h>
#include <math.h>
#include <stdint.h>

#define NQv   262144
#define EMB   128
#define HWPX  30720
#define IMW   320
#define NIc   300
#define NIM   384
#define HIDN  512
#define NEGV  -1e30f

// ---------------- device scratch ----------------
__device__ float g_full[(size_t)NQv*EMB];
__device__ float g_se  [(size_t)NQv*EMB];
__device__ float g_sp  [(size_t)NQv*EMB];
__device__ float g_bA  [(size_t)NQv*EMB];
__device__ float g_hid [(size_t)NQv*HIDN];

__device__ float g_wx[HWPX], g_wy[HWPX], g_wz[HWPX];
__device__ int   g_kidx[NIc];
__device__ float g_sk[NIc];
__device__ int   g_mids[HWPX];
__device__ int   g_marea[NIc], g_parea[NIc], g_inter[NIc];
__device__ int   g_selj[NIc], g_k2idx[NIc];
__device__ float g_xyz[NIc*3];
__device__ int   g_fidx[NQv];
__device__ int   g_inv [NQv];
__device__ int   g_bcnt[512], g_boff[512];
__device__ int   g_ints[8];   // 0=Nk 1=Ns 2=Nf 3=fovmode

__device__ float gi_q[NIM*EMB], gi_p[NIM*EMB], gi_qin[NIM*EMB], gi_Qp[NIM*EMB],
                 gi_Kp[NIM*EMB], gi_Vp[NIM*EMB];

// attn0 split-K partials
__device__ float g_pm  [4*NIM*16];
__device__ float g_pl  [4*NIM*16];
__device__ float g_pacc[4*NIM*16*32];

// ---------------- fov dtype auto-detect ----------------
__global__ void k_fovdetect(const unsigned int* __restrict__ fm){
    __shared__ int fl[6];
    if (threadIdx.x < 6) fl[threadIdx.x] = 0;
    __syncthreads();
    for (int i = threadIdx.x; i < 32768; i += 256){
        unsigned w = fm[i];
        if (w > 1u)                      atomicOr(&fl[0], 1);
        if (w != 0u && w != 0x3f800000u) atomicOr(&fl[1], 1);
        unsigned b0=w&255u,b1=(w>>8)&255u,b2=(w>>16)&255u,b3=w>>24;
        if (b0>1u||b1>1u||b2>1u||b3>1u)  atomicOr(&fl[2], 1);
        if ((i & 1) && w)                atomicOr(&fl[3], 1);
    }
    __syncthreads();
    if (threadIdx.x == 0){
        int mode;
        if      (!fl[0]) mode = fl[3] ? 0 : 1;
        else if (!fl[1]) mode = 2;
        else if (!fl[2]) mode = 4;
        else             mode = 3;
        g_ints[3] = mode;
    }
}

__device__ __forceinline__ int fov_get(const void* fm, int n){
    switch (g_ints[3]){
        case 0:  return ((const int*)fm)[n] != 0;
        case 1:  return ((const long long*)fm)[n] != 0;
        case 2:  return ((const float*)fm)[n] != 0.f;
        case 3:  return ((const double*)fm)[n] != 0.0;
        default: return ((const unsigned char*)fm)[n] != 0;
    }
}

// ---------------- fov compaction ----------------
__global__ void k_fovcount(const void* __restrict__ fm){
    int idx = blockIdx.x*512 + threadIdx.x;
    int f = fov_get(fm, idx);
    int c = __syncthreads_count(f);
    if (threadIdx.x==0) g_bcnt[blockIdx.x]=c;
}
__global__ void k_fovscan(){
    __shared__ int s[512];
    int t=threadIdx.x;
    int mine=g_bcnt[t];
    s[t]=mine; __syncthreads();
    for (int off=1; off<512; off<<=1){
        int v = (t>=off) ? s[t-off] : 0;
        __syncthreads(); s[t]+=v; __syncthreads();
    }
    g_boff[t]=s[t]-mine;
    if (t==511) g_ints[2]=s[511];
}
__global__ void k_fovscatter(const void* __restrict__ fm){
    __shared__ int s[512];
    int t=threadIdx.x;
    int idx=blockIdx.x*512+t;
    int f=fov_get(fm, idx);
    s[t]=f; __syncthreads();
    for (int off=1; off<512; off<<=1){
        int v = (t>=off) ? s[t-off] : 0;
        __syncthreads(); s[t]+=v; __syncthreads();
    }
    if (f){
        int r = g_boff[blockIdx.x] + s[t]-1;
        g_fidx[r] = idx;
        g_inv[idx] = r;
    }
}

// ---------------- scene embed base + fused fov gather ----------------
__global__ void k_buildfull(const void* __restrict__ fm,
                            const float* __restrict__ sew, const float* __restrict__ x3d,
                            const float* __restrict__ posw, const float* __restrict__ vo){
    __shared__ float tsh[32][33];
    int n0 = blockIdx.x*32, c0 = blockIdx.y*32;
    int tx = threadIdx.x, ty = threadIdx.y;
    #pragma unroll
    for (int yy=0; yy<32; yy+=8)
        tsh[ty+yy][tx] = x3d[(size_t)(c0+ty+yy)*NQv + n0+tx];
    __syncthreads();
    float v0 = vo[0], v1 = vo[1], v2 = vo[2];
    #pragma unroll
    for (int yy=0; yy<32; yy+=8){
        int n=n0+ty+yy, c=c0+tx;
        float v = sew[(size_t)n*EMB+c] + tsh[tx][ty+yy];
        g_full[(size_t)n*EMB+c] = v;
        if (fov_get(fm, n)){
            int r = g_inv[n];
            g_se[(size_t)r*EMB+c] = v;
            int i = n>>11, j = (n>>4)&127, k = n&15;
            float px=(i+0.5f)*0.2f+v0, py=(j+0.5f)*0.2f+v1, pz=(k+0.5f)*0.2f+v2;
            g_sp[(size_t)r*EMB+c] = posw[c*3+0]*px + posw[c*3+1]*py + posw[c*3+2]*pz;
        }
    }
}

// ---------------- world coords (with inlined matrix inverses) ----------------
__global__ void k_world(const float* __restrict__ depth,
                        const float* __restrict__ Km, const float* __restrict__ Em){
    __shared__ float Ki[9], Ei[16];
    if (threadIdx.x == 0){
        {   double a=Km[0],b=Km[1],c=Km[2],d=Km[3],e=Km[4],f=Km[5],g=Km[6],h=Km[7],i=Km[8];
            double det = a*(e*i-f*h) - b*(d*i-f*g) + c*(d*h-e*g);
            double inv[9] = { e*i-f*h, c*h-b*i, b*f-c*e,
                              f*g-d*i, a*i-c*g, c*d-a*f,
                              d*h-e*g, b*g-a*h, a*e-b*d };
            for (int t=0;t<9;t++) Ki[t] = (float)(inv[t]/det);
        }
        {   double M[4][8];
            for (int i=0;i<4;i++) for (int j=0;j<4;j++){ M[i][j]=Em[i*4+j]; M[i][4+j]=(i==j)?1.0:0.0; }
            for (int col=0; col<4; col++){
                int piv=col;
                for (int r=col+1;r<4;r++) if (fabs(M[r][col])>fabs(M[piv][col])) piv=r;
                if (piv!=col) for (int j=0;j<8;j++){ double t=M[col][j]; M[col][j]=M[piv][j]; M[piv][j]=t; }
                double pv=M[col][col];
                for (int j=0;j<8;j++) M[col][j]/=pv;
                for (int r=0;r<4;r++) if (r!=col){
                    double f=M[r][col];
                    for (int j=0;j<8;j++) M[r][j]-=f*M[col][j];
                }
            }
            for (int i=0;i<4;i++) for (int j=0;j<4;j++) Ei[i*4+j]=(float)M[i][4+j];
        }
    }
    __syncthreads();
    int p = blockIdx.x*256 + threadIdx.x;
    if (p >= HWPX) return;
    int y = p / IMW, x = p % IMW;
    float d = depth[p];
    float vx = (float)x*4.0f*d, vy = (float)y*4.0f*d, vz = d;
    float c0 = Ki[0]*vx + Ki[1]*vy + Ki[2]*vz;
    float c1 = Ki[3]*vx + Ki[4]*vy + Ki[5]*vz;
    float c2 = Ki[6]*vx + Ki[7]*vy + Ki[8]*vz;
    g_wx[p] = Ei[0]*c0 + Ei[1]*c1 + Ei[2] *c2 + Ei[3];
    g_wy[p] = Ei[4]*c0 + Ei[5]*c1 + Ei[6] *c2 + Ei[7];
    g_wz[p] = Ei[8]*c0 + Ei[9]*c1 + Ei[10]*c2 + Ei[11];
}

// ---------------- instance scoring ----------------
__global__ void k_scores(const float* __restrict__ logits){
    __shared__ float sc[NIc];
    __shared__ int   kp[NIc];
    int i = threadIdx.x;
    if (i < NIc){
        float z[21]; float mx = NEGV;
        #pragma unroll
        for (int j=0;j<21;j++){
            float s = 1.f/(1.f+expf(-logits[i*21+j]));
            z[j] = s/0.06f;
            if (z[j]>mx) mx=z[j];
        }
        float sum=0.f, me=0.f;
        #pragma unroll
        for (int j=0;j<21;j++){ float e=expf(z[j]-mx); sum+=e; if (e>me) me=e; }
        float score = me/sum;
        sc[i]=score; kp[i]=(score>0.25f)?1:0;
    }
    __syncthreads();
    if (i==0){
        int c=0;
        for (int j=0;j<NIc;j++) if (kp[j]){ g_kidx[c]=j; g_sk[c]=sc[j]; c++; }
        g_ints[0]=c;
    }
}

__global__ void k_mids(const float* __restrict__ pm){
    int p = blockIdx.x*256 + threadIdx.x;
    if (p >= HWPX) return;
    int Nk = g_ints[0];
    float best = NEGV; int arg = 0;
    for (int j=0;j<Nk;j++){
        int inst = g_kidx[j];
        float v = g_sk[j] * (1.f/(1.f+expf(-pm[(size_t)inst*HWPX+p])));
        if (v > best){ best=v; arg=j; }
    }
    g_mids[p]=arg;
}

__global__ void k_areas(const float* __restrict__ pm){
    int j = blockIdx.x;
    if (j >= g_ints[0]) return;
    int inst = g_kidx[j];
    int cm=0,cp=0,ci=0;
    for (int p=threadIdx.x; p<HWPX; p+=256){
        int mm = (g_mids[p]==j);
        int pb = (pm[(size_t)inst*HWPX+p] >= 0.f);
        cm+=mm; cp+=pb; ci+=(mm&&pb);
    }
    __shared__ int r0[256],r1[256],r2[256];
    int t=threadIdx.x; r0[t]=cm; r1[t]=cp; r2[t]=ci; __syncthreads();
    for (int off=128; off>0; off>>=1){
        if (t<off){ r0[t]+=r0[t+off]; r1[t]+=r1[t+off]; r2[t]+=r2[t+off]; }
        __syncthreads();
    }
    if (t==0){ g_marea[j]=r0[0]; g_parea[j]=r1[0]; g_inter[j]=r2[0]; }
}

__global__ void k_select(){
    if (threadIdx.x | blockIdx.x) return;
    int Nk=g_ints[0], ns=0;
    for (int j=0;j<Nk;j++){
        if (g_inter[j] > 0 && ((float)g_marea[j]/(float)g_parea[j]) >= 0.8f){
            g_selj[ns]=j; g_k2idx[ns]=g_kidx[j]; ns++;
        }
    }
    g_ints[1]=ns;
}

__global__ void k_xyz(const float* __restrict__ pm){
    int s = blockIdx.x;
    if (s >= g_ints[1]) return;
    int j = g_selj[s], inst = g_k2idx[s];
    float sx=0,sy=0,sz=0;
    for (int p=threadIdx.x;p<HWPX;p+=256){
        if (g_mids[p]==j && pm[(size_t)inst*HWPX+p] >= 0.f){
            sx+=g_wx[p]; sy+=g_wy[p]; sz+=g_wz[p];
        }
    }
    __shared__ float r0[256],r1[256],r2[256];
    int t=threadIdx.x; r0[t]=sx; r1[t]=sy; r2[t]=sz; __syncthreads();
    for (int off=128; off>0; off>>=1){
        if (t<off){ r0[t]+=r0[t+off]; r1[t]+=r1[t+off]; r2[t]+=r2[t+off]; }
        __syncthreads();
    }
    if (t==0){ g_xyz[s*3+0]=r0[0]; g_xyz[s*3+1]=r1[0]; g_xyz[s*3+2]=r2[0]; }
}

__global__ void k_instbuild(const float* __restrict__ queries,
                            const float* __restrict__ instposw,
                            const float* __restrict__ posw){
    int s = blockIdx.x;
    if (s >= g_ints[1]) return;
    int c = threadIdx.x;
    int inst = g_k2idx[s];
    float x=g_xyz[s*3+0], y=g_xyz[s*3+1], z=g_xyz[s*3+2];
    gi_q[s*EMB+c] = queries[inst*EMB+c];
    gi_p[s*EMB+c] = instposw[inst*EMB+c] + posw[c*3+0]*x + posw[c*3+1]*y + posw[c*3+2]*z;
}

// ---------------- bf16x2-split tensor-core GEMM core ----------------
__device__ __forceinline__ void bsplit2(float x0, float x1, unsigned &hi, unsigned &lo){
    __nv_bfloat16 h0 = __float2bfloat16(x0);
    __nv_bfloat16 h1 = __float2bfloat16(x1);
    __nv_bfloat16 l0 = __float2bfloat16(x0 - __bfloat162float(h0));
    __nv_bfloat16 l1 = __float2bfloat16(x1 - __bfloat162float(h1));
    unsigned short uh0 = *reinterpret_cast<unsigned short*>(&h0);
    unsigned short uh1 = *reinterpret_cast<unsigned short*>(&h1);
    unsigned short ul0 = *reinterpret_cast<unsigned short*>(&l0);
    unsigned short ul1 = *reinterpret_cast<unsigned short*>(&l1);
    hi = (unsigned)uh0 | ((unsigned)uh1 << 16);
    lo = (unsigned)ul0 | ((unsigned)ul1 << 16);
}
#define MMA_BF16(d0,d1,d2,d3,a0,a1,a2,a3,b0,b1) \
  asm volatile("mma.sync.aligned.m16n8k16.row.col.f32.bf16.bf16.f32 " \
    "{%0,%1,%2,%3},{%4,%5,%6,%7},{%8,%9},{%0,%1,%2,%3};" \
    : "+f"(d0),"+f"(d1),"+f"(d2),"+f"(d3) \
    : "r"(a0),"r"(a1),"r"(a2),"r"(a3),"r"(b0),"r"(b1))

#define SMS 136

// store SRC[8] (K offsets kq..kq+7, row row_l) into buffer arrays
#define STORE_SPLIT_TO(SRC, AH, AL) do { \
    int kq2_ = kq >> 1; \
    _Pragma("unroll") \
    for (int jj=0;jj<4;jj++){ \
        unsigned hv, lv; \
        bsplit2(SRC[2*jj], SRC[2*jj+1], hv, lv); \
        AH[kq2_+jj][row_l] = hv; \
        AL[kq2_+jj][row_l] = lv; \
    } \
} while(0)

#define LOAD_FRAGS_AND_MMA_FROM(AH, AL, WH, WL) do { \
    unsigned ah[2][4], al[2][4]; \
    _Pragma("unroll") \
    for (int mt=0;mt<2;mt++){ \
        int r0 = mb + mt*16 + g; \
        ah[mt][0]=AH[t][r0];   ah[mt][1]=AH[t][r0+8]; \
        ah[mt][2]=AH[t+4][r0]; ah[mt][3]=AH[t+4][r0+8]; \
        al[mt][0]=AL[t][r0];   al[mt][1]=AL[t][r0+8]; \
        al[mt][2]=AL[t+4][r0]; al[mt][3]=AL[t+4][r0+8]; \
    } \
    _Pragma("unroll") \
    for (int j=0;j<8;j++){ \
        int nc = nb + j*8 + g; \
        unsigned bh0=WH[t][nc], bh1=WH[t+4][nc]; \
        unsigned bl0=WL[t][nc], bl1=WL[t+4][nc]; \
        _Pragma("unroll") \
        for (int mt=0;mt<2;mt++){ \
            MMA_BF16(acc[mt][j][0],acc[mt][j][1],acc[mt][j][2],acc[mt][j][3], \
                     al[mt][0],al[mt][1],al[mt][2],al[mt][3], bh0,bh1); \
            MMA_BF16(acc[mt][j][0],acc[mt][j][1],acc[mt][j][2],acc[mt][j][3], \
                     ah[mt][0],ah[mt][1],ah[mt][2],ah[mt][3], bl0,bl1); \
            MMA_BF16(acc[mt][j][0],acc[mt][j][1],acc[mt][j][2],acc[mt][j][3], \
                     ah[mt][0],ah[mt][1],ah[mt][2],ah[mt][3], bh0,bh1); \
        } \
    } \
} while(0)

// Generic GEMM (128x128 tiles, double-buffered smem, single barrier per K-tile):
// C = (A (+A2 if bn<a2lim)) @ W^T + bias, opt relu, dual out C0/C1.
__global__ void __launch_bounds__(256,2) k_gemm(
    const float* __restrict__ A, const float* __restrict__ A2, int a2lim,
    const float* __restrict__ W, const float* __restrict__ bias,
    float* __restrict__ C0, float* __restrict__ C1,
    int N, int K, int relu, int cstride)
{
    __shared__ unsigned Ah[2][8][SMS], Al[2][8][SMS], Wh[2][8][SMS], Wl[2][8][SMS];
    int M = g_ints[2];
    int bn = blockIdx.x * 128;
    const float* A2u = (A2 && bn < a2lim) ? A2 : NULL;
    int tid = threadIdx.x;
    int row_l = tid & 127;
    int kq    = (tid >> 7) * 8;
    int w = tid >> 5, lane = tid & 31;
    int g = lane >> 2, t = lane & 3;
    int mb = (w >> 1) * 32, nb = (w & 1) * 64;

    int b = 0;
    for (int bm = blockIdx.y*128; bm < M; bm += gridDim.y*128){
        float acc[2][8][4];
        #pragma unroll
        for (int mt=0;mt<2;mt++)
            #pragma unroll
            for (int j=0;j<8;j++)
                #pragma unroll
                for (int q=0;q<4;q++) acc[mt][j][q]=0.f;

        for (int kt=0; kt<K; kt+=16){
            {
                int arow = bm + row_l;
                float va[8];
                if (arow < M){
                    const float* pa = &A[(size_t)arow*K + kt + kq];
                    float4 v0 = *(const float4*)pa, v1 = *(const float4*)(pa+4);
                    va[0]=v0.x; va[1]=v0.y; va[2]=v0.z; va[3]=v0.w;
                    va[4]=v1.x; va[5]=v1.y; va[6]=v1.z; va[7]=v1.w;
                    if (A2u){
                        const float* pb = &A2u[(size_t)arow*K + kt + kq];
                        float4 u0 = *(const float4*)pb, u1 = *(const float4*)(pb+4);
                        va[0]+=u0.x; va[1]+=u0.y; va[2]+=u0.z; va[3]+=u0.w;
                        va[4]+=u1.x; va[5]+=u1.y; va[6]+=u1.z; va[7]+=u1.w;
                    }
                } else {
                    #pragma unroll
                    for (int j=0;j<8;j++) va[j]=0.f;
                }
                STORE_SPLIT_TO(va, Ah[b], Al[b]);
                const float* pw = &W[(size_t)(bn+row_l)*K + kt + kq];
                float4 w0 = *(const float4*)pw, w1 = *(const float4*)(pw+4);
                float vw[8] = {w0.x,w0.y,w0.z,w0.w,w1.x,w1.y,w1.z,w1.w};
                STORE_SPLIT_TO(vw, Wh[b], Wl[b]);
            }
            __syncthreads();
            LOAD_FRAGS_AND_MMA_FROM(Ah[b], Al[b], Wh[b], Wl[b]);
            b ^= 1;   // next stores go to the other buffer; no trailing barrier needed
        }
        #pragma unroll
        for (int mt=0;mt<2;mt++){
            #pragma unroll
            for (int j=0;j<8;j++){
                int col = bn + nb + j*8 + t*2;
                float b0v = bias[col], b1v = bias[col+1];
                float* Cd = C0; int cc = col;
                if (C1 && col >= 128){ Cd = C1; cc = col - 128; }
                int r0 = bm + mb + mt*16 + g;
                if (r0 < M){
                    float v0 = acc[mt][j][0] + b0v;
                    float v1 = acc[mt][j][1] + b1v;
                    if (relu){ v0=fmaxf(v0,0.f); v1=fmaxf(v1,0.f); }
                    *(float2*)&Cd[(size_t)r0*cstride + cc] = make_float2(v0,v1);
                }
                int r1 = r0 + 8;
                if (r1 < M){
                    float v0 = acc[mt][j][2] + b0v;
                    float v1 = acc[mt][j][3] + b1v;
                    if (relu){ v0=fmaxf(v0,0.f); v1=fmaxf(v1,0.f); }
                    *(float2*)&Cd[(size_t)r1*cstride + cc] = make_float2(v0,v1);
                }
            }
        }
    }
}

// GEMM (N=128) + bias + residual(s) + LayerNorm fused epilogue (double-buffered).
__global__ void __launch_bounds__(256,2) k_gemm_ln(
    const float* __restrict__ A, const float* __restrict__ W,
    const float* __restrict__ bias,
    const float* __restrict__ res1, const float* __restrict__ res2,
    const float* __restrict__ gam, const float* __restrict__ bet,
    float* __restrict__ C, int K)
{
    __shared__ unsigned Ah[2][8][SMS], Al[2][8][SMS], Wh[2][8][SMS], Wl[2][8][SMS];
    __shared__ float ssum[128][2], ssq[128][2];
    int M = g_ints[2];
    int tid = threadIdx.x;
    int row_l = tid & 127;
    int kq    = (tid >> 7) * 8;
    int w = tid >> 5, lane = tid & 31;
    int g = lane >> 2, t = lane & 3;
    int mb = (w >> 1) * 32, nb = (w & 1) * 64;

    int b = 0;
    for (int bm = blockIdx.y*128; bm < M; bm += gridDim.y*128){
        float acc[2][8][4];
        #pragma unroll
        for (int mt=0;mt<2;mt++)
            #pragma unroll
            for (int j=0;j<8;j++)
                #pragma unroll
                for (int q=0;q<4;q++) acc[mt][j][q]=0.f;

        for (int kt=0; kt<K; kt+=16){
            {
                int arow = bm + row_l;
                float va[8];
                if (arow < M){
                    const float* pa = &A[(size_t)arow*K + kt + kq];
                    float4 v0 = *(const float4*)pa, v1 = *(const float4*)(pa+4);
                    va[0]=v0.x; va[1]=v0.y; va[2]=v0.z; va[3]=v0.w;
                    va[4]=v1.x; va[5]=v1.y; va[6]=v1.z; va[7]=v1.w;
                } else {
                    #pragma unroll
                    for (int j=0;j<8;j++) va[j]=0.f;
                }
                STORE_SPLIT_TO(va, Ah[b], Al[b]);
                const float* pw = &W[(size_t)row_l*K + kt + kq];
                float4 w0 = *(const float4*)pw, w1 = *(const float4*)(pw+4);
                float vw[8] = {w0.x,w0.y,w0.z,w0.w,w1.x,w1.y,w1.z,w1.w};
                STORE_SPLIT_TO(vw, Wh[b], Wl[b]);
            }
            __syncthreads();
            LOAD_FRAGS_AND_MMA_FROM(Ah[b], Al[b], Wh[b], Wl[b]);
            b ^= 1;
        }
        #pragma unroll
        for (int mt=0;mt<2;mt++){
            #pragma unroll
            for (int j=0;j<8;j++){
                int col = nb + j*8 + t*2;
                float b0v = bias[col], b1v = bias[col+1];
                int r0 = bm + mb + mt*16 + g, r1 = r0 + 8;
                size_t o0 = (size_t)r0*EMB + col, o1 = (size_t)r1*EMB + col;
                float a0 = acc[mt][j][0] + b0v + res1[o0];
                float a1 = acc[mt][j][1] + b1v + res1[o0+1];
                float a2 = acc[mt][j][2] + b0v + res1[o1];
                float a3 = acc[mt][j][3] + b1v + res1[o1+1];
                if (res2){
                    a0 += res2[o0]; a1 += res2[o0+1];
                    a2 += res2[o1]; a3 += res2[o1+1];
                }
                acc[mt][j][0]=a0; acc[mt][j][1]=a1; acc[mt][j][2]=a2; acc[mt][j][3]=a3;
            }
        }
        float s_[2][2], q_[2][2];
        #pragma unroll
        for (int mt=0;mt<2;mt++){
            s_[mt][0]=0.f; s_[mt][1]=0.f; q_[mt][0]=0.f; q_[mt][1]=0.f;
            #pragma unroll
            for (int j=0;j<8;j++){
                s_[mt][0]+=acc[mt][j][0]+acc[mt][j][1];
                q_[mt][0]+=acc[mt][j][0]*acc[mt][j][0]+acc[mt][j][1]*acc[mt][j][1];
                s_[mt][1]+=acc[mt][j][2]+acc[mt][j][3];
                q_[mt][1]+=acc[mt][j][2]*acc[mt][j][2]+acc[mt][j][3]*acc[mt][j][3];
            }
        }
        #pragma unroll
        for (int off=1; off<4; off<<=1){
            #pragma unroll
            for (int mt=0;mt<2;mt++){
                s_[mt][0]+=__shfl_xor_sync(0xffffffffu, s_[mt][0], off);
                s_[mt][1]+=__shfl_xor_sync(0xffffffffu, s_[mt][1], off);
                q_[mt][0]+=__shfl_xor_sync(0xffffffffu, q_[mt][0], off);
                q_[mt][1]+=__shfl_xor_sync(0xffffffffu, q_[mt][1], off);
            }
        }
        if (t == 0){
            #pragma unroll
            for (int mt=0;mt<2;mt++){
                int rA = mb + mt*16 + g, rB = rA + 8;
                ssum[rA][w&1]=s_[mt][0]; ssq[rA][w&1]=q_[mt][0];
                ssum[rB][w&1]=s_[mt][1]; ssq[rB][w&1]=q_[mt][1];
            }
        }
        __syncthreads();
        #pragma unroll
        for (int mt=0;mt<2;mt++){
            int rA = mb + mt*16 + g, rB = rA + 8;
            float su0 = ssum[rA][0]+ssum[rA][1], sq0 = ssq[rA][0]+ssq[rA][1];
            float su1 = ssum[rB][0]+ssum[rB][1], sq1 = ssq[rB][0]+ssq[rB][1];
            float mu0 = su0/128.f, mu1 = su1/128.f;
            float rs0 = rsqrtf(sq0/128.f - mu0*mu0 + 1e-5f);
            float rs1 = rsqrtf(sq1/128.f - mu1*mu1 + 1e-5f);
            int r0 = bm + rA, r1 = bm + rB;
            #pragma unroll
            for (int j=0;j<8;j++){
                int col = nb + j*8 + t*2;
                float g0 = gam[col], g1 = gam[col+1];
                float e0 = bet[col], e1 = bet[col+1];
                if (r0 < M){
                    float v0 = (acc[mt][j][0]-mu0)*rs0*g0+e0;
                    float v1 = (acc[mt][j][1]-mu0)*rs0*g1+e1;
                    *(float2*)&C[(size_t)r0*EMB + col] = make_float2(v0,v1);
                }
                if (r1 < M){
                    float v0 = (acc[mt][j][2]-mu1)*rs1*g0+e0;
                    float v1 = (acc[mt][j][3]-mu1)*rs1*g1+e1;
                    *(float2*)&C[(size_t)r1*EMB + col] = make_float2(v0,v1);
                }
            }
        }
        __syncthreads();
    }
}

// ---------------- fused branch-1 attention megakernel ----------------
#define B1A_AH   0
#define B1A_AL   4352
#define B1A_WH   8704
#define B1A_WL   13056
#define B1A_SQ   17408
#define B1A_SO   (17408 + 67584)
#define B1A_SSUM (17408 + 135168)
#define B1A_SSQ  (17408 + 135168 + 1024)
#define B1_SMEM  (17408 + 135168 + 2048)
__global__ void __launch_bounds__(256) k_b1attn(
    const float* __restrict__ se, const float* __restrict__ sp,
    const float* __restrict__ Wq, const float* __restrict__ bq,
    const float* __restrict__ Wo, const float* __restrict__ bo,
    const float* __restrict__ gam, const float* __restrict__ bet,
    float* __restrict__ X)
{
    extern __shared__ unsigned char dsm[];
    unsigned (*AhS)[SMS] = (unsigned (*)[SMS])(dsm + B1A_AH);
    unsigned (*AlS)[SMS] = (unsigned (*)[SMS])(dsm + B1A_AL);
    unsigned (*WhS)[SMS] = (unsigned (*)[SMS])(dsm + B1A_WH);
    unsigned (*WlS)[SMS] = (unsigned (*)[SMS])(dsm + B1A_WL);
    float (*sQ)[132]    = (float (*)[132])(dsm + B1A_SQ);
    float (*sO)[132]    = (float (*)[132])(dsm + B1A_SO);
    float (*ssum)[2]    = (float (*)[2])(dsm + B1A_SSUM);
    float (*ssq)[2]     = (float (*)[2])(dsm + B1A_SSQ);

    int M = g_ints[2];
    int Ns = g_ints[1];
    int tid = threadIdx.x;
    int row_l = tid & 127;
    int kq    = (tid >> 7) * 8;
    int w = tid >> 5, lane = tid & 31;
    int g = lane >> 2, t = lane & 3;
    int mb = (w >> 1) * 32, nb = (w & 1) * 64;

    for (int bm = blockIdx.y*128; bm < M; bm += gridDim.y*128){
        // ===== stage 1: Qp = (se+sp) @ Wq^T + bq -> sQ =====
        float acc[2][8][4];
        #pragma unroll
        for (int mt=0;mt<2;mt++)
            #pragma unroll
            for (int j=0;j<8;j++)
                #pragma unroll
                for (int q=0;q<4;q++) acc[mt][j][q]=0.f;

        for (int kt=0; kt<EMB; kt+=16){
            {
                int arow = bm + row_l;
                float va[8];
                if (arow < M){
                    const float* pa = &se[(size_t)arow*EMB + kt + kq];
                    const float* pb = &sp[(size_t)arow*EMB + kt + kq];
                    float4 v0 = *(const float4*)pa, v1 = *(const float4*)(pa+4);
                    float4 u0 = *(const float4*)pb, u1 = *(const float4*)(pb+4);
                    va[0]=v0.x+u0.x; va[1]=v0.y+u0.y; va[2]=v0.z+u0.z; va[3]=v0.w+u0.w;
                    va[4]=v1.x+u1.x; va[5]=v1.y+u1.y; va[6]=v1.z+u1.z; va[7]=v1.w+u1.w;
                } else {
                    #pragma unroll
                    for (int j=0;j<8;j++) va[j]=0.f;
                }
                STORE_SPLIT_TO(va, AhS, AlS);
                const float* pw = &Wq[(size_t)row_l*EMB + kt + kq];
                float4 w0 = *(const float4*)pw, w1 = *(const float4*)(pw+4);
                float vw[8] = {w0.x,w0.y,w0.z,w0.w,w1.x,w1.y,w1.z,w1.w};
                STORE_SPLIT_TO(vw, WhS, WlS);
            }
            __syncthreads();
            LOAD_FRAGS_AND_MMA_FROM(AhS, AlS, WhS, WlS);
            __syncthreads();
        }
        #pragma unroll
        for (int mt=0;mt<2;mt++){
            #pragma unroll
            for (int j=0;j<8;j++){
                int col = nb + j*8 + t*2;
                int ph = ((col>>5)*33) + (col&31);
                float b0v = bq[col], b1v = bq[col+1];
                int rA = mb + mt*16 + g, rB = rA + 8;
                sQ[rA][ph]   = acc[mt][j][0] + b0v;
                sQ[rA][ph+1] = acc[mt][j][1] + b1v;
                sQ[rB][ph]   = acc[mt][j][2] + b0v;
                sQ[rB][ph+1] = acc[mt][j][3] + b1v;
            }
        }
        __syncthreads();

        // ===== stage 2: per-row per-head attention over Ns inst keys =====
        #pragma unroll
        for (int half=0; half<2; half++){
            int row = half*64 + (tid>>2);
            int h = tid & 3;
            int pb = h*33;
            float m = NEGV, l = 0.f, pacc[32];
            #pragma unroll
            for (int d=0;d<32;d++) pacc[d]=0.f;
            for (int j=0;j<Ns;j++){
                const float* kr = &gi_Kp[j*EMB + h*32];
                float dsum = 0.f;
                #pragma unroll
                for (int d=0;d<32;d++) dsum += sQ[row][pb+d]*kr[d];
                dsum *= 0.17677669529663687f;
                float nm = fmaxf(m, dsum);
                float fac = expf(m-nm), e = expf(dsum-nm);
                l = l*fac + e;
                const float* vr = &gi_Vp[j*EMB + h*32];
                #pragma unroll
                for (int d=0;d<32;d++) pacc[d] = pacc[d]*fac + e*vr[d];
                m = nm;
            }
            float inv = 1.f/l;
            #pragma unroll
            for (int d=0;d<32;d++) sO[row][h*32+d] = pacc[d]*inv;
        }
        __syncthreads();

        // ===== stage 3: out = sO @ Wo^T + bo; x = LN(se+sp+out) =====
        #pragma unroll
        for (int mt=0;mt<2;mt++)
            #pragma unroll
            for (int j=0;j<8;j++)
                #pragma unroll
                for (int q=0;q<4;q++) acc[mt][j][q]=0.f;

        for (int kt=0; kt<EMB; kt+=16){
            {
                float va[8];
                #pragma unroll
                for (int j=0;j<8;j++) va[j] = sO[row_l][kt+kq+j];
                STORE_SPLIT_TO(va, AhS, AlS);
                const float* pw = &Wo[(size_t)row_l*EMB + kt + kq];
                float4 w0 = *(const float4*)pw, w1 = *(const float4*)(pw+4);
                float vw[8] = {w0.x,w0.y,w0.z,w0.w,w1.x,w1.y,w1.z,w1.w};
                STORE_SPLIT_TO(vw, WhS, WlS);
            }
            __syncthreads();
            LOAD_FRAGS_AND_MMA_FROM(AhS, AlS, WhS, WlS);
            __syncthreads();
        }
        #pragma unroll
        for (int mt=0;mt<2;mt++){
            #pragma unroll
            for (int j=0;j<8;j++){
                int col = nb + j*8 + t*2;
                float b0v = bo[col], b1v = bo[col+1];
                int r0 = bm + mb + mt*16 + g, r1 = r0 + 8;
                size_t o0 = (size_t)min(r0, M-1)*EMB + col;
                size_t o1 = (size_t)min(r1, M-1)*EMB + col;
                float a0 = acc[mt][j][0] + b0v + se[o0] + sp[o0];
                float a1 = acc[mt][j][1] + b1v + se[o0+1] + sp[o0+1];
                float a2 = acc[mt][j][2] + b0v + se[o1] + sp[o1];
                float a3 = acc[mt][j][3] + b1v + se[o1+1] + sp[o1+1];
                acc[mt][j][0]=a0; acc[mt][j][1]=a1; acc[mt][j][2]=a2; acc[mt][j][3]=a3;
            }
        }
        float s_[2][2], q_[2][2];
        #pragma unroll
        for (int mt=0;mt<2;mt++){
            s_[mt][0]=0.f; s_[mt][1]=0.f; q_[mt][0]=0.f; q_[mt][1]=0.f;
            #pragma unroll
            for (int j=0;j<8;j++){
                s_[mt][0]+=acc[mt][j][0]+acc[mt][j][1];
                q_[mt][0]+=acc[mt][j][0]*acc[mt][j][0]+acc[mt][j][1]*acc[mt][j][1];
                s_[mt][1]+=acc[mt][j][2]+acc[mt][j][3];
                q_[mt][1]+=acc[mt][j][2]*acc[mt][j][2]+acc[mt][j][3]*acc[mt][j][3];
            }
        }
        #pragma unroll
        for (int off=1; off<4; off<<=1){
            #pragma unroll
            for (int mt=0;mt<2;mt++){
                s_[mt][0]+=__shfl_xor_sync(0xffffffffu, s_[mt][0], off);
                s_[mt][1]+=__shfl_xor_sync(0xffffffffu, s_[mt][1], off);
                q_[mt][0]+=__shfl_xor_sync(0xffffffffu, q_[mt][0], off);
                q_[mt][1]+=__shfl_xor_sync(0xffffffffu, q_[mt][1], off);
            }
        }
        if (t == 0){
            #pragma unroll
            for (int mt=0;mt<2;mt++){
                int rA = mb + mt*16 + g, rB = rA + 8;
                ssum[rA][w&1]=s_[mt][0]; ssq[rA][w&1]=q_[mt][0];
                ssum[rB][w&1]=s_[mt][1]; ssq[rB][w&1]=q_[mt][1];
            }
        }
        __syncthreads();
        #pragma unroll
        for (int mt=0;mt<2;mt++){
            int rA = mb + mt*16 + g, rB = rA + 8;
            float su0 = ssum[rA][0]+ssum[rA][1], sq0 = ssq[rA][0]+ssq[rA][1];
            float su1 = ssum[rB][0]+ssum[rB][1], sq1 = ssq[rB][0]+ssq[rB][1];
            float mu0 = su0/128.f, mu1 = su1/128.f;
            float rs0 = rsqrtf(sq0/128.f - mu0*mu0 + 1e-5f);
            float rs1 = rsqrtf(sq1/128.f - mu1*mu1 + 1e-5f);
            int r0 = bm + rA, r1 = bm + rB;
            #pragma unroll
            for (int j=0;j<8;j++){
                int col = nb + j*8 + t*2;
                float g0 = gam[col], g1 = gam[col+1];
                float e0 = bet[col], e1 = bet[col+1];
                if (r0 < M){
                    float v0 = (acc[mt][j][0]-mu0)*rs0*g0+e0;
                    float v1 = (acc[mt][j][1]-mu0)*rs0*g1+e1;
                    *(float2*)&X[(size_t)r0*EMB + col] = make_float2(v0,v1);
                }
                if (r1 < M){
                    float v0 = (acc[mt][j][2]-mu1)*rs1*g0+e0;
                    float v1 = (acc[mt][j][3]-mu1)*rs1*g1+e1;
                    *(float2*)&X[(size_t)r1*EMB + col] = make_float2(v0,v1);
                }
            }
        }
        __syncthreads();
    }
}

// ---------------- fused instance-side kernels ----------------
__device__ __forceinline__ float block_ln(float x, float* red, int t,
                                          const float* g, const float* b){
    red[t]=x; __syncthreads();
    for (int off=64; off>0; off>>=1){ if (t<off) red[t]+=red[t+off]; __syncthreads(); }
    float mu = red[0]/128.f; __syncthreads();
    float d = x-mu;
    red[t]=d*d; __syncthreads();
    for (int off=64; off>0; off>>=1){ if (t<off) red[t]+=red[t+off]; __syncthreads(); }
    float var = red[0]/128.f; __syncthreads();
    return d*rsqrtf(var+1e-5f)*g[t]+b[t];
}

__global__ void k_inst_pre(const float* __restrict__ wq, const float* __restrict__ bq){
    int s = blockIdx.x;
    if (s >= g_ints[1]) return;
    int c = threadIdx.x;
    __shared__ float sq_[EMB];
    float qin = gi_q[s*EMB+c] + gi_p[s*EMB+c];
    gi_qin[s*EMB+c] = qin;
    sq_[c] = qin; __syncthreads();
    float acc = bq[c];
    const float* wr = &wq[c*EMB];
    #pragma unroll 8
    for (int k=0;k<EMB;k++) acc += sq_[k]*wr[k];
    gi_Qp[s*EMB+c] = acc;
}

__global__ void k_inst_kv(const float* __restrict__ wk, const float* __restrict__ bk,
                          const float* __restrict__ wv, const float* __restrict__ bv){
    int s = blockIdx.x;
    if (s >= g_ints[1]) return;
    int c = threadIdx.x;
    __shared__ float sqin[EMB], sq_[EMB];
    float qv = gi_q[s*EMB+c];
    sqin[c] = qv + gi_p[s*EMB+c];
    sq_[c]  = qv;
    __syncthreads();
    float ak = bk[c], av = bv[c];
    const float* wkr = &wk[c*EMB];
    const float* wvr = &wv[c*EMB];
    #pragma unroll 8
    for (int k=0;k<EMB;k++){ ak += sqin[k]*wkr[k]; av += sq_[k]*wvr[k]; }
    gi_Kp[s*EMB+c] = ak;
    gi_Vp[s*EMB+c] = av;
}

__global__ void k_inst_post(const float* __restrict__ wo, const float* __restrict__ bo,
                            const float* __restrict__ lg, const float* __restrict__ lb,
                            const float* __restrict__ w1, const float* __restrict__ b1,
                            const float* __restrict__ w2, const float* __restrict__ b2){
    int s = blockIdx.x;
    if (s >= g_ints[1]) return;
    int c = threadIdx.x;
    __shared__ float sO[EMB], sx[EMB], sh[HIDN], red[EMB];
    {
        int h = c>>5, lane = c&31;
        float m = NEGV, l = 0.f, a = 0.f;
        int base = (h*NIM + s)*16;
        for (int ck=0;ck<16;ck++){
            float mc = g_pm[base+ck], lc = g_pl[base+ck];
            float ac = g_pacc[(size_t)(base+ck)*32 + lane];
            float nm = fmaxf(m, mc);
            float fa = expf(m-nm), fb = expf(mc-nm);
            l = l*fa + lc*fb;
            a = a*fa + ac*fb;
            m = nm;
        }
        sO[c] = a/l;
    }
    __syncthreads();
    float mha = bo[c];
    {
        const float* wr = &wo[c*EMB];
        #pragma unroll 8
        for (int k=0;k<EMB;k++) mha += sO[k]*wr[k];
    }
    float x = block_ln(gi_qin[s*EMB+c] + mha, red, c, lg, lb);
    sx[c] = x; __syncthreads();
    #pragma unroll
    for (int hc=c; hc<HIDN; hc+=EMB){
        float a = b1[hc];
        const float* wr = &w1[hc*EMB];
        #pragma unroll 8
        for (int k=0;k<EMB;k++) a += sx[k]*wr[k];
        sh[hc] = fmaxf(a, 0.f);
    }
    __syncthreads();
    float h2 = b2[c];
    {
        const float* wr = &w2[c*HIDN];
        #pragma unroll 8
        for (int k=0;k<HIDN;k++) h2 += sh[k]*wr[k];
    }
    gi_q[s*EMB+c] = block_ln(x + h2, red, c, lg+EMB, lb+EMB);
}

// ---------------- attn0: 8 instances per block, smem-staged K/V ----------------
__global__ void __launch_bounds__(256) k_attn0p(
    const float* __restrict__ Kp, const float* __restrict__ Vp)
{
    int Ns = g_ints[1];
    int grp = blockIdx.z;
    if (grp*8 >= Ns) return;
    int h = blockIdx.y;
    int c = blockIdx.x;           // 0..15
    int Nf = g_ints[2];
    int chunk = (Nf + 15) >> 4;
    int k0 = c*chunk, k1 = min(k0+chunk, Nf);
    int tid = threadIdx.x;
    int is = tid >> 5, kl = tid & 31;
    int s = grp*8 + is;
    bool sok = (s < Ns);

    __shared__ float sK[32][33], sV[32][33];
    __shared__ float sq[8][33];
    if (sok) sq[is][kl] = gi_Qp[s*EMB + h*32 + kl] * 0.17677669529663687f;
    __syncthreads();

    float m = NEGV, l = 0.f, acc[32];
    #pragma unroll
    for (int d=0;d<32;d++) acc[d]=0.f;

    for (int kp0 = k0; kp0 < k1; kp0 += 32){
        int nk = min(32, k1 - kp0);
        for (int idx = tid; idx < nk*32; idx += 256){
            int kr = idx >> 5, d = idx & 31;
            sK[kr][d] = Kp[(size_t)(kp0+kr)*EMB + h*32 + d];
            sV[kr][d] = Vp[(size_t)(kp0+kr)*EMB + h*32 + d];
        }
        __syncthreads();
        if (sok && kl < nk){
            float dsum = 0.f;
            #pragma unroll
            for (int d=0;d<32;d++) dsum += sq[is][d]*sK[kl][d];
            float nm = fmaxf(m, dsum);
            float fac = expf(m - nm);
            float e = expf(dsum - nm);
            l = l*fac + e;
            #pragma unroll
            for (int d=0;d<32;d++) acc[d] = acc[d]*fac + e*sV[kl][d];
            m = nm;
        }
        __syncthreads();
    }

    #pragma unroll
    for (int off=16; off>0; off>>=1){
        float mo = __shfl_xor_sync(0xffffffffu, m, off);
        float lo = __shfl_xor_sync(0xffffffffu, l, off);
        float nm = fmaxf(m, mo);
        float fa = expf(m-nm), fb = expf(mo-nm);
        l = l*fa + lo*fb;
        #pragma unroll
        for (int d=0;d<32;d++){
            float ao = __shfl_xor_sync(0xffffffffu, acc[d], off);
            acc[d] = acc[d]*fa + ao*fb;
        }
        m = nm;
    }

    if (sok){
        int pi = (h*NIM + s)*16 + c;
        if (kl == 0){ g_pm[pi] = m; g_pl[pi] = l; }
        #pragma unroll
        for (int d=0;d<32;d++)
            if (kl == d) g_pacc[(size_t)pi*32 + d] = acc[d];
    }
}

// ---------------- final conv (with inline scatter of se) ----------------
__global__ void __launch_bounds__(256) k_conv(
    const void* __restrict__ fm,
    const float* __restrict__ cw, const float* __restrict__ cb,
    float* __restrict__ out)
{
    __shared__ float scw[20*EMB];
    __shared__ float scb[20];
    for (int i=threadIdx.x; i<20*EMB; i+=256) scw[i]=cw[i];
    if (threadIdx.x < 20) scb[threadIdx.x]=cb[threadIdx.x];
    __syncthreads();
    int n = blockIdx.x*256 + threadIdx.x;
    const float* row;
    if (fov_get(fm, n)) row = &g_se[(size_t)g_inv[n]*EMB];
    else                row = &g_full[(size_t)n*EMB];
    float r[EMB/4][4];
    #pragma unroll
    for (int k=0;k<EMB/4;k++) *(float4*)r[k] = *(const float4*)&row[k*4];
    for (int o=0;o<20;o++){
        float acc = scb[o];
        const float* w = &scw[o*EMB];
        #pragma unroll
        for (int k=0;k<EMB;k++) acc += r[k>>2][k&3]*w[k];
        out[(size_t)o*NQv + n] = acc;
    }
}

// ---------------- host ----------------
extern "C" void kernel_launch(void* const* d_in, const int* in_sizes, int n_in,
                              void* d_out, int out_size)
{
    const float* queries  = (const float*)d_in[0];
    const float* logits   = (const float*)d_in[1];
    const float* pmasks   = (const float*)d_in[2];
    const float* x3d      = (const float*)d_in[3];
    const float* depth    = (const float*)d_in[4];
    const float* Km       = (const float*)d_in[5];
    const float* Em       = (const float*)d_in[6];
    const float* vo       = (const float*)d_in[7];
    const void * fov      = (const void *)d_in[8];
    const float* sew      = (const float*)d_in[9];
    const float* instposw = (const float*)d_in[10];
    const float* posw     = (const float*)d_in[11];
    const float* convw    = (const float*)d_in[12];
    const float* convb    = (const float*)d_in[13];
    const float* attw     = (const float*)d_in[14];
    const float* attb     = (const float*)d_in[15];
    const float* lng      = (const float*)d_in[16];
    const float* lnb      = (const float*)d_in[17];
    const float* fw1      = (const float*)d_in[18];
    const float* fb1      = (const float*)d_in[19];
    const float* fw2      = (const float*)d_in[20];
    const float* fb2      = (const float*)d_in[21];
    float* out = (float*)d_out;

    float *p_se, *p_sp, *p_bA, *p_hid;
    cudaGetSymbolAddress((void**)&p_se,  g_se);
    cudaGetSymbolAddress((void**)&p_sp,  g_sp);
    cudaGetSymbolAddress((void**)&p_bA,  g_bA);
    cudaGetSymbolAddress((void**)&p_hid, g_hid);

    cudaFuncSetAttribute(k_b1attn, cudaFuncAttributeMaxDynamicSharedMemorySize, B1_SMEM);

    const size_t E2 = (size_t)EMB*EMB;

    // fov + scene setup
    k_fovdetect<<<1,256>>>((const unsigned int*)fov);
    k_fovcount<<<512,512>>>(fov);
    k_fovscan<<<1,512>>>();
    k_fovscatter<<<512,512>>>(fov);
    dim3 tb(32,8);
    k_buildfull<<<dim3(NQv/32,4),tb>>>(fov, sew, x3d, posw, vo);

    // instance post-processing
    k_world<<<(HWPX+255)/256,256>>>(depth, Km, Em);
    k_scores<<<1,320>>>(logits);
    k_mids<<<(HWPX+255)/256,256>>>(pmasks);
    k_areas<<<NIc,256>>>(pmasks);
    k_select<<<1,1>>>();
    k_xyz<<<NIc,256>>>(pmasks);
    k_instbuild<<<NIc,128>>>(queries, instposw, posw);

    for (int i=0;i<2;i++){
        // ---- branch 0: update inst queries (attend to scene) ----
        const float* aw = attw + (size_t)(i*2+0)*4*E2;
        const float* ab = attb + (size_t)(i*2+0)*4*EMB;
        const float* g0 = lng + (size_t)(i*2+0)*2*EMB;
        const float* b0 = lnb + (size_t)(i*2+0)*2*EMB;
        k_inst_pre<<<NIc,128>>>(aw+0*E2, ab+0*EMB);
        k_gemm<<<dim3(2,148),256>>>(p_se, p_sp, 128, aw+1*E2, ab+1*EMB,
                                    p_bA, p_hid, 256, EMB, 0, EMB);   // Kp->bA, Vp->hid
        k_attn0p<<<dim3(16,4,(NIc+7)/8),256>>>(p_bA, p_hid);
        k_inst_post<<<NIc,128>>>(aw+3*E2, ab+3*EMB, g0, b0,
                                 fw1+(size_t)(i*2+0)*HIDN*EMB, fb1+(size_t)(i*2+0)*HIDN,
                                 fw2+(size_t)(i*2+0)*EMB*HIDN, fb2+(size_t)(i*2+0)*EMB);

        // ---- branch 1: update scene embeddings (attend to inst) ----
        aw = attw + (size_t)(i*2+1)*4*E2;
        ab = attb + (size_t)(i*2+1)*4*EMB;
        const float* g1v = lng + (size_t)(i*2+1)*2*EMB;
        const float* b1v = lnb + (size_t)(i*2+1)*2*EMB;
        k_inst_kv<<<NIc,128>>>(aw+1*E2, ab+1*EMB, aw+2*E2, ab+2*EMB);
        k_b1attn<<<dim3(1,512),256,B1_SMEM>>>(p_se, p_sp,
                                              aw+0*E2, ab+0*EMB,
                                              aw+3*E2, ab+3*EMB,
                                              g1v, b1v, p_bA);        // x -> bA
        k_gemm<<<dim3(4,148),256>>>(p_bA, NULL, 0,
                                    fw1+(size_t)(i*2+1)*HIDN*EMB, fb1+(size_t)(i*2+1)*HIDN,
                                    p_hid, NULL, HIDN, EMB, 1, HIDN);
        k_gemm_ln<<<dim3(1,296),256>>>(p_hid,
                                       fw2+(size_t)(i*2+1)*EMB*HIDN, fb2+(size_t)(i*2+1)*EMB,
                                       p_bA, NULL, g1v+EMB, b1v+EMB, p_se, HIDN);
    }

    k_conv<<<NQv/256,256>>>(fov, convw, convb, out);
}

// round 15
// speedup vs baseline: 1.1088x; 1.0053x over previous
#include <cuda_runtime.h>
#include <cuda_bf16.h>
#include <math.h>
#include <stdint.h>

#define NQv   262144
#define EMB   128
#define HWPX  30720
#define IMW   320
#define NIc   300
#define NIM   384
#define HIDN  512
#define NEGV  -1e30f

// ---------------- device scratch ----------------
__device__ float g_full[(size_t)NQv*EMB];
__device__ float g_se  [(size_t)NQv*EMB];
__device__ float g_sp  [(size_t)NQv*EMB];
__device__ float g_bA  [(size_t)NQv*EMB];
__device__ float g_hid [(size_t)NQv*HIDN];

__device__ float g_wx[HWPX], g_wy[HWPX], g_wz[HWPX];
__device__ int   g_kidx[NIc];
__device__ float g_sk[NIc];
__device__ int   g_mids[HWPX];
__device__ int   g_marea[NIc], g_parea[NIc], g_inter[NIc];
__device__ int   g_selj[NIc], g_k2idx[NIc];
__device__ float g_xyz[NIc*3];
__device__ int   g_fidx[NQv];
__device__ int   g_inv [NQv];
__device__ int   g_bcnt[512], g_boff[512];
__device__ int   g_ints[8];   // 0=Nk 1=Ns 2=Nf 3=fovmode

__device__ float gi_q[NIM*EMB], gi_p[NIM*EMB], gi_qin[NIM*EMB], gi_Qp[NIM*EMB],
                 gi_Kp[NIM*EMB], gi_Vp[NIM*EMB];

// attn0 split-K partials
__device__ float g_pm  [4*NIM*16];
__device__ float g_pl  [4*NIM*16];
__device__ float g_pacc[4*NIM*16*32];

// ---------------- fov dtype auto-detect ----------------
__global__ void k_fovdetect(const unsigned int* __restrict__ fm){
    __shared__ int fl[6];
    if (threadIdx.x < 6) fl[threadIdx.x] = 0;
    __syncthreads();
    for (int i = threadIdx.x; i < 32768; i += 256){
        unsigned w = fm[i];
        if (w > 1u)                      atomicOr(&fl[0], 1);
        if (w != 0u && w != 0x3f800000u) atomicOr(&fl[1], 1);
        unsigned b0=w&255u,b1=(w>>8)&255u,b2=(w>>16)&255u,b3=w>>24;
        if (b0>1u||b1>1u||b2>1u||b3>1u)  atomicOr(&fl[2], 1);
        if ((i & 1) && w)                atomicOr(&fl[3], 1);
    }
    __syncthreads();
    if (threadIdx.x == 0){
        int mode;
        if      (!fl[0]) mode = fl[3] ? 0 : 1;
        else if (!fl[1]) mode = 2;
        else if (!fl[2]) mode = 4;
        else             mode = 3;
        g_ints[3] = mode;
    }
}

__device__ __forceinline__ int fov_get(const void* fm, int n){
    switch (g_ints[3]){
        case 0:  return ((const int*)fm)[n] != 0;
        case 1:  return ((const long long*)fm)[n] != 0;
        case 2:  return ((const float*)fm)[n] != 0.f;
        case 3:  return ((const double*)fm)[n] != 0.0;
        default: return ((const unsigned char*)fm)[n] != 0;
    }
}

// ---------------- fov compaction ----------------
__global__ void k_fovcount(const void* __restrict__ fm){
    int idx = blockIdx.x*512 + threadIdx.x;
    int f = fov_get(fm, idx);
    int c = __syncthreads_count(f);
    if (threadIdx.x==0) g_bcnt[blockIdx.x]=c;
}
__global__ void k_fovscan(){
    __shared__ int s[512];
    int t=threadIdx.x;
    int mine=g_bcnt[t];
    s[t]=mine; __syncthreads();
    for (int off=1; off<512; off<<=1){
        int v = (t>=off) ? s[t-off] : 0;
        __syncthreads(); s[t]+=v; __syncthreads();
    }
    g_boff[t]=s[t]-mine;
    if (t==511) g_ints[2]=s[511];
}
__global__ void k_fovscatter(const void* __restrict__ fm){
    __shared__ int s[512];
    int t=threadIdx.x;
    int idx=blockIdx.x*512+t;
    int f=fov_get(fm, idx);
    s[t]=f; __syncthreads();
    for (int off=1; off<512; off<<=1){
        int v = (t>=off) ? s[t-off] : 0;
        __syncthreads(); s[t]+=v; __syncthreads();
    }
    if (f){
        int r = g_boff[blockIdx.x] + s[t]-1;
        g_fidx[r] = idx;
        g_inv[idx] = r;
    }
}

// ---------------- scene embed base + fused fov gather ----------------
__global__ void k_buildfull(const void* __restrict__ fm,
                            const float* __restrict__ sew, const float* __restrict__ x3d,
                            const float* __restrict__ posw, const float* __restrict__ vo){
    __shared__ float tsh[32][33];
    int n0 = blockIdx.x*32, c0 = blockIdx.y*32;
    int tx = threadIdx.x, ty = threadIdx.y;
    #pragma unroll
    for (int yy=0; yy<32; yy+=8)
        tsh[ty+yy][tx] = x3d[(size_t)(c0+ty+yy)*NQv + n0+tx];
    __syncthreads();
    float v0 = vo[0], v1 = vo[1], v2 = vo[2];
    #pragma unroll
    for (int yy=0; yy<32; yy+=8){
        int n=n0+ty+yy, c=c0+tx;
        float v = sew[(size_t)n*EMB+c] + tsh[tx][ty+yy];
        g_full[(size_t)n*EMB+c] = v;
        if (fov_get(fm, n)){
            int r = g_inv[n];
            g_se[(size_t)r*EMB+c] = v;
            int i = n>>11, j = (n>>4)&127, k = n&15;
            float px=(i+0.5f)*0.2f+v0, py=(j+0.5f)*0.2f+v1, pz=(k+0.5f)*0.2f+v2;
            g_sp[(size_t)r*EMB+c] = posw[c*3+0]*px + posw[c*3+1]*py + posw[c*3+2]*pz;
        }
    }
}

// ---------------- world coords (with inlined matrix inverses) ----------------
__global__ void k_world(const float* __restrict__ depth,
                        const float* __restrict__ Km, const float* __restrict__ Em){
    __shared__ float Ki[9], Ei[16];
    if (threadIdx.x == 0){
        {   double a=Km[0],b=Km[1],c=Km[2],d=Km[3],e=Km[4],f=Km[5],g=Km[6],h=Km[7],i=Km[8];
            double det = a*(e*i-f*h) - b*(d*i-f*g) + c*(d*h-e*g);
            double inv[9] = { e*i-f*h, c*h-b*i, b*f-c*e,
                              f*g-d*i, a*i-c*g, c*d-a*f,
                              d*h-e*g, b*g-a*h, a*e-b*d };
            for (int t=0;t<9;t++) Ki[t] = (float)(inv[t]/det);
        }
        {   double M[4][8];
            for (int i=0;i<4;i++) for (int j=0;j<4;j++){ M[i][j]=Em[i*4+j]; M[i][4+j]=(i==j)?1.0:0.0; }
            for (int col=0; col<4; col++){
                int piv=col;
                for (int r=col+1;r<4;r++) if (fabs(M[r][col])>fabs(M[piv][col])) piv=r;
                if (piv!=col) for (int j=0;j<8;j++){ double t=M[col][j]; M[col][j]=M[piv][j]; M[piv][j]=t; }
                double pv=M[col][col];
                for (int j=0;j<8;j++) M[col][j]/=pv;
                for (int r=0;r<4;r++) if (r!=col){
                    double f=M[r][col];
                    for (int j=0;j<8;j++) M[r][j]-=f*M[col][j];
                }
            }
            for (int i=0;i<4;i++) for (int j=0;j<4;j++) Ei[i*4+j]=(float)M[i][4+j];
        }
    }
    __syncthreads();
    int p = blockIdx.x*256 + threadIdx.x;
    if (p >= HWPX) return;
    int y = p / IMW, x = p % IMW;
    float d = depth[p];
    float vx = (float)x*4.0f*d, vy = (float)y*4.0f*d, vz = d;
    float c0 = Ki[0]*vx + Ki[1]*vy + Ki[2]*vz;
    float c1 = Ki[3]*vx + Ki[4]*vy + Ki[5]*vz;
    float c2 = Ki[6]*vx + Ki[7]*vy + Ki[8]*vz;
    g_wx[p] = Ei[0]*c0 + Ei[1]*c1 + Ei[2] *c2 + Ei[3];
    g_wy[p] = Ei[4]*c0 + Ei[5]*c1 + Ei[6] *c2 + Ei[7];
    g_wz[p] = Ei[8]*c0 + Ei[9]*c1 + Ei[10]*c2 + Ei[11];
}

// ---------------- instance scoring ----------------
__global__ void k_scores(const float* __restrict__ logits){
    __shared__ float sc[NIc];
    __shared__ int   kp[NIc];
    int i = threadIdx.x;
    if (i < NIc){
        float z[21]; float mx = NEGV;
        #pragma unroll
        for (int j=0;j<21;j++){
            float s = 1.f/(1.f+expf(-logits[i*21+j]));
            z[j] = s/0.06f;
            if (z[j]>mx) mx=z[j];
        }
        float sum=0.f, me=0.f;
        #pragma unroll
        for (int j=0;j<21;j++){ float e=expf(z[j]-mx); sum+=e; if (e>me) me=e; }
        float score = me/sum;
        sc[i]=score; kp[i]=(score>0.25f)?1:0;
    }
    __syncthreads();
    if (i==0){
        int c=0;
        for (int j=0;j<NIc;j++) if (kp[j]){ g_kidx[c]=j; g_sk[c]=sc[j]; c++; }
        g_ints[0]=c;
    }
}

__global__ void k_mids(const float* __restrict__ pm){
    int p = blockIdx.x*256 + threadIdx.x;
    if (p >= HWPX) return;
    int Nk = g_ints[0];
    float best = NEGV; int arg = 0;
    for (int j=0;j<Nk;j++){
        int inst = g_kidx[j];
        float v = g_sk[j] * (1.f/(1.f+expf(-pm[(size_t)inst*HWPX+p])));
        if (v > best){ best=v; arg=j; }
    }
    g_mids[p]=arg;
}

__global__ void k_areas(const float* __restrict__ pm){
    int j = blockIdx.x;
    if (j >= g_ints[0]) return;
    int inst = g_kidx[j];
    int cm=0,cp=0,ci=0;
    for (int p=threadIdx.x; p<HWPX; p+=256){
        int mm = (g_mids[p]==j);
        int pb = (pm[(size_t)inst*HWPX+p] >= 0.f);
        cm+=mm; cp+=pb; ci+=(mm&&pb);
    }
    __shared__ int r0[256],r1[256],r2[256];
    int t=threadIdx.x; r0[t]=cm; r1[t]=cp; r2[t]=ci; __syncthreads();
    for (int off=128; off>0; off>>=1){
        if (t<off){ r0[t]+=r0[t+off]; r1[t]+=r1[t+off]; r2[t]+=r2[t+off]; }
        __syncthreads();
    }
    if (t==0){ g_marea[j]=r0[0]; g_parea[j]=r1[0]; g_inter[j]=r2[0]; }
}

__global__ void k_select(){
    if (threadIdx.x | blockIdx.x) return;
    int Nk=g_ints[0], ns=0;
    for (int j=0;j<Nk;j++){
        if (g_inter[j] > 0 && ((float)g_marea[j]/(float)g_parea[j]) >= 0.8f){
            g_selj[ns]=j; g_k2idx[ns]=g_kidx[j]; ns++;
        }
    }
    g_ints[1]=ns;
}

__global__ void k_xyz(const float* __restrict__ pm){
    int s = blockIdx.x;
    if (s >= g_ints[1]) return;
    int j = g_selj[s], inst = g_k2idx[s];
    float sx=0,sy=0,sz=0;
    for (int p=threadIdx.x;p<HWPX;p+=256){
        if (g_mids[p]==j && pm[(size_t)inst*HWPX+p] >= 0.f){
            sx+=g_wx[p]; sy+=g_wy[p]; sz+=g_wz[p];
        }
    }
    __shared__ float r0[256],r1[256],r2[256];
    int t=threadIdx.x; r0[t]=sx; r1[t]=sy; r2[t]=sz; __syncthreads();
    for (int off=128; off>0; off>>=1){
        if (t<off){ r0[t]+=r0[t+off]; r1[t]+=r1[t+off]; r2[t]+=r2[t+off]; }
        __syncthreads();
    }
    if (t==0){ g_xyz[s*3+0]=r0[0]; g_xyz[s*3+1]=r1[0]; g_xyz[s*3+2]=r2[0]; }
}

__global__ void k_instbuild(const float* __restrict__ queries,
                            const float* __restrict__ instposw,
                            const float* __restrict__ posw){
    int s = blockIdx.x;
    if (s >= g_ints[1]) return;
    int c = threadIdx.x;
    int inst = g_k2idx[s];
    float x=g_xyz[s*3+0], y=g_xyz[s*3+1], z=g_xyz[s*3+2];
    gi_q[s*EMB+c] = queries[inst*EMB+c];
    gi_p[s*EMB+c] = instposw[inst*EMB+c] + posw[c*3+0]*x + posw[c*3+1]*y + posw[c*3+2]*z;
}

// ---------------- bf16x2-split tensor-core GEMM core ----------------
__device__ __forceinline__ void bsplit2(float x0, float x1, unsigned &hi, unsigned &lo){
    __nv_bfloat16 h0 = __float2bfloat16(x0);
    __nv_bfloat16 h1 = __float2bfloat16(x1);
    __nv_bfloat16 l0 = __float2bfloat16(x0 - __bfloat162float(h0));
    __nv_bfloat16 l1 = __float2bfloat16(x1 - __bfloat162float(h1));
    unsigned short uh0 = *reinterpret_cast<unsigned short*>(&h0);
    unsigned short uh1 = *reinterpret_cast<unsigned short*>(&h1);
    unsigned short ul0 = *reinterpret_cast<unsigned short*>(&l0);
    unsigned short ul1 = *reinterpret_cast<unsigned short*>(&l1);
    hi = (unsigned)uh0 | ((unsigned)uh1 << 16);
    lo = (unsigned)ul0 | ((unsigned)ul1 << 16);
}
#define MMA_BF16(d0,d1,d2,d3,a0,a1,a2,a3,b0,b1) \
  asm volatile("mma.sync.aligned.m16n8k16.row.col.f32.bf16.bf16.f32 " \
    "{%0,%1,%2,%3},{%4,%5,%6,%7},{%8,%9},{%0,%1,%2,%3};" \
    : "+f"(d0),"+f"(d1),"+f"(d2),"+f"(d3) \
    : "r"(a0),"r"(a1),"r"(a2),"r"(a3),"r"(b0),"r"(b1))

#define SMS 136

// store SRC[8] (K offsets kq..kq+7, row row_l) into buffer arrays
#define STORE_SPLIT_TO(SRC, AH, AL) do { \
    int kq2_ = kq >> 1; \
    _Pragma("unroll") \
    for (int jj=0;jj<4;jj++){ \
        unsigned hv, lv; \
        bsplit2(SRC[2*jj], SRC[2*jj+1], hv, lv); \
        AH[kq2_+jj][row_l] = hv; \
        AL[kq2_+jj][row_l] = lv; \
    } \
} while(0)

#define LOAD_FRAGS_AND_MMA_FROM(AH, AL, WH, WL) do { \
    unsigned ah[2][4], al[2][4]; \
    _Pragma("unroll") \
    for (int mt=0;mt<2;mt++){ \
        int r0 = mb + mt*16 + g; \
        ah[mt][0]=AH[t][r0];   ah[mt][1]=AH[t][r0+8]; \
        ah[mt][2]=AH[t+4][r0]; ah[mt][3]=AH[t+4][r0+8]; \
        al[mt][0]=AL[t][r0];   al[mt][1]=AL[t][r0+8]; \
        al[mt][2]=AL[t+4][r0]; al[mt][3]=AL[t+4][r0+8]; \
    } \
    _Pragma("unroll") \
    for (int j=0;j<8;j++){ \
        int nc = nb + j*8 + g; \
        unsigned bh0=WH[t][nc], bh1=WH[t+4][nc]; \
        unsigned bl0=WL[t][nc], bl1=WL[t+4][nc]; \
        _Pragma("unroll") \
        for (int mt=0;mt<2;mt++){ \
            MMA_BF16(acc[mt][j][0],acc[mt][j][1],acc[mt][j][2],acc[mt][j][3], \
                     al[mt][0],al[mt][1],al[mt][2],al[mt][3], bh0,bh1); \
            MMA_BF16(acc[mt][j][0],acc[mt][j][1],acc[mt][j][2],acc[mt][j][3], \
                     ah[mt][0],ah[mt][1],ah[mt][2],ah[mt][3], bl0,bl1); \
            MMA_BF16(acc[mt][j][0],acc[mt][j][1],acc[mt][j][2],acc[mt][j][3], \
                     ah[mt][0],ah[mt][1],ah[mt][2],ah[mt][3], bh0,bh1); \
        } \
    } \
} while(0)

// Generic GEMM (128x128 tiles, double-buffered smem, single barrier per K-tile):
// C = (A (+A2 if bn<a2lim)) @ W^T + bias, opt relu, dual out C0/C1.
__global__ void __launch_bounds__(256,2) k_gemm(
    const float* __restrict__ A, const float* __restrict__ A2, int a2lim,
    const float* __restrict__ W, const float* __restrict__ bias,
    float* __restrict__ C0, float* __restrict__ C1,
    int N, int K, int relu, int cstride)
{
    __shared__ unsigned Ah[2][8][SMS], Al[2][8][SMS], Wh[2][8][SMS], Wl[2][8][SMS];
    int M = g_ints[2];
    int bn = blockIdx.x * 128;
    const float* A2u = (A2 && bn < a2lim) ? A2 : NULL;
    int tid = threadIdx.x;
    int row_l = tid & 127;
    int kq    = (tid >> 7) * 8;
    int w = tid >> 5, lane = tid & 31;
    int g = lane >> 2, t = lane & 3;
    int mb = (w >> 1) * 32, nb = (w & 1) * 64;

    int b = 0;
    for (int bm = blockIdx.y*128; bm < M; bm += gridDim.y*128){
        float acc[2][8][4];
        #pragma unroll
        for (int mt=0;mt<2;mt++)
            #pragma unroll
            for (int j=0;j<8;j++)
                #pragma unroll
                for (int q=0;q<4;q++) acc[mt][j][q]=0.f;

        for (int kt=0; kt<K; kt+=16){
            {
                int arow = bm + row_l;
                float va[8];
                if (arow < M){
                    const float* pa = &A[(size_t)arow*K + kt + kq];
                    float4 v0 = *(const float4*)pa, v1 = *(const float4*)(pa+4);
                    va[0]=v0.x; va[1]=v0.y; va[2]=v0.z; va[3]=v0.w;
                    va[4]=v1.x; va[5]=v1.y; va[6]=v1.z; va[7]=v1.w;
                    if (A2u){
                        const float* pb = &A2u[(size_t)arow*K + kt + kq];
                        float4 u0 = *(const float4*)pb, u1 = *(const float4*)(pb+4);
                        va[0]+=u0.x; va[1]+=u0.y; va[2]+=u0.z; va[3]+=u0.w;
                        va[4]+=u1.x; va[5]+=u1.y; va[6]+=u1.z; va[7]+=u1.w;
                    }
                } else {
                    #pragma unroll
                    for (int j=0;j<8;j++) va[j]=0.f;
                }
                STORE_SPLIT_TO(va, Ah[b], Al[b]);
                const float* pw = &W[(size_t)(bn+row_l)*K + kt + kq];
                float4 w0 = *(const float4*)pw, w1 = *(const float4*)(pw+4);
                float vw[8] = {w0.x,w0.y,w0.z,w0.w,w1.x,w1.y,w1.z,w1.w};
                STORE_SPLIT_TO(vw, Wh[b], Wl[b]);
            }
            __syncthreads();
            LOAD_FRAGS_AND_MMA_FROM(Ah[b], Al[b], Wh[b], Wl[b]);
            b ^= 1;   // next stores go to the other buffer; no trailing barrier needed
        }
        #pragma unroll
        for (int mt=0;mt<2;mt++){
            #pragma unroll
            for (int j=0;j<8;j++){
                int col = bn + nb + j*8 + t*2;
                float b0v = bias[col], b1v = bias[col+1];
                float* Cd = C0; int cc = col;
                if (C1 && col >= 128){ Cd = C1; cc = col - 128; }
                int r0 = bm + mb + mt*16 + g;
                if (r0 < M){
                    float v0 = acc[mt][j][0] + b0v;
                    float v1 = acc[mt][j][1] + b1v;
                    if (relu){ v0=fmaxf(v0,0.f); v1=fmaxf(v1,0.f); }
                    *(float2*)&Cd[(size_t)r0*cstride + cc] = make_float2(v0,v1);
                }
                int r1 = r0 + 8;
                if (r1 < M){
                    float v0 = acc[mt][j][2] + b0v;
                    float v1 = acc[mt][j][3] + b1v;
                    if (relu){ v0=fmaxf(v0,0.f); v1=fmaxf(v1,0.f); }
                    *(float2*)&Cd[(size_t)r1*cstride + cc] = make_float2(v0,v1);
                }
            }
        }
    }
}

// GEMM (N=128) + bias + residual(s) + LayerNorm fused epilogue (double-buffered).
__global__ void __launch_bounds__(256,2) k_gemm_ln(
    const float* __restrict__ A, const float* __restrict__ W,
    const float* __restrict__ bias,
    const float* __restrict__ res1, const float* __restrict__ res2,
    const float* __restrict__ gam, const float* __restrict__ bet,
    float* __restrict__ C, int K)
{
    __shared__ unsigned Ah[2][8][SMS], Al[2][8][SMS], Wh[2][8][SMS], Wl[2][8][SMS];
    __shared__ float ssum[128][2], ssq[128][2];
    int M = g_ints[2];
    int tid = threadIdx.x;
    int row_l = tid & 127;
    int kq    = (tid >> 7) * 8;
    int w = tid >> 5, lane = tid & 31;
    int g = lane >> 2, t = lane & 3;
    int mb = (w >> 1) * 32, nb = (w & 1) * 64;

    int b = 0;
    for (int bm = blockIdx.y*128; bm < M; bm += gridDim.y*128){
        float acc[2][8][4];
        #pragma unroll
        for (int mt=0;mt<2;mt++)
            #pragma unroll
            for (int j=0;j<8;j++)
                #pragma unroll
                for (int q=0;q<4;q++) acc[mt][j][q]=0.f;

        for (int kt=0; kt<K; kt+=16){
            {
                int arow = bm + row_l;
                float va[8];
                if (arow < M){
                    const float* pa = &A[(size_t)arow*K + kt + kq];
                    float4 v0 = *(const float4*)pa, v1 = *(const float4*)(pa+4);
                    va[0]=v0.x; va[1]=v0.y; va[2]=v0.z; va[3]=v0.w;
                    va[4]=v1.x; va[5]=v1.y; va[6]=v1.z; va[7]=v1.w;
                } else {
                    #pragma unroll
                    for (int j=0;j<8;j++) va[j]=0.f;
                }
                STORE_SPLIT_TO(va, Ah[b], Al[b]);
                const float* pw = &W[(size_t)row_l*K + kt + kq];
                float4 w0 = *(const float4*)pw, w1 = *(const float4*)(pw+4);
                float vw[8] = {w0.x,w0.y,w0.z,w0.w,w1.x,w1.y,w1.z,w1.w};
                STORE_SPLIT_TO(vw, Wh[b], Wl[b]);
            }
            __syncthreads();
            LOAD_FRAGS_AND_MMA_FROM(Ah[b], Al[b], Wh[b], Wl[b]);
            b ^= 1;
        }
        #pragma unroll
        for (int mt=0;mt<2;mt++){
            #pragma unroll
            for (int j=0;j<8;j++){
                int col = nb + j*8 + t*2;
                float b0v = bias[col], b1v = bias[col+1];
                int r0 = bm + mb + mt*16 + g, r1 = r0 + 8;
                size_t o0 = (size_t)r0*EMB + col, o1 = (size_t)r1*EMB + col;
                float a0 = acc[mt][j][0] + b0v + res1[o0];
                float a1 = acc[mt][j][1] + b1v + res1[o0+1];
                float a2 = acc[mt][j][2] + b0v + res1[o1];
                float a3 = acc[mt][j][3] + b1v + res1[o1+1];
                if (res2){
                    a0 += res2[o0]; a1 += res2[o0+1];
                    a2 += res2[o1]; a3 += res2[o1+1];
                }
                acc[mt][j][0]=a0; acc[mt][j][1]=a1; acc[mt][j][2]=a2; acc[mt][j][3]=a3;
            }
        }
        float s_[2][2], q_[2][2];
        #pragma unroll
        for (int mt=0;mt<2;mt++){
            s_[mt][0]=0.f; s_[mt][1]=0.f; q_[mt][0]=0.f; q_[mt][1]=0.f;
            #pragma unroll
            for (int j=0;j<8;j++){
                s_[mt][0]+=acc[mt][j][0]+acc[mt][j][1];
                q_[mt][0]+=acc[mt][j][0]*acc[mt][j][0]+acc[mt][j][1]*acc[mt][j][1];
                s_[mt][1]+=acc[mt][j][2]+acc[mt][j][3];
                q_[mt][1]+=acc[mt][j][2]*acc[mt][j][2]+acc[mt][j][3]*acc[mt][j][3];
            }
        }
        #pragma unroll
        for (int off=1; off<4; off<<=1){
            #pragma unroll
            for (int mt=0;mt<2;mt++){
                s_[mt][0]+=__shfl_xor_sync(0xffffffffu, s_[mt][0], off);
                s_[mt][1]+=__shfl_xor_sync(0xffffffffu, s_[mt][1], off);
                q_[mt][0]+=__shfl_xor_sync(0xffffffffu, q_[mt][0], off);
                q_[mt][1]+=__shfl_xor_sync(0xffffffffu, q_[mt][1], off);
            }
        }
        if (t == 0){
            #pragma unroll
            for (int mt=0;mt<2;mt++){
                int rA = mb + mt*16 + g, rB = rA + 8;
                ssum[rA][w&1]=s_[mt][0]; ssq[rA][w&1]=q_[mt][0];
                ssum[rB][w&1]=s_[mt][1]; ssq[rB][w&1]=q_[mt][1];
            }
        }
        __syncthreads();
        #pragma unroll
        for (int mt=0;mt<2;mt++){
            int rA = mb + mt*16 + g, rB = rA + 8;
            float su0 = ssum[rA][0]+ssum[rA][1], sq0 = ssq[rA][0]+ssq[rA][1];
            float su1 = ssum[rB][0]+ssum[rB][1], sq1 = ssq[rB][0]+ssq[rB][1];
            float mu0 = su0/128.f, mu1 = su1/128.f;
            float rs0 = rsqrtf(sq0/128.f - mu0*mu0 + 1e-5f);
            float rs1 = rsqrtf(sq1/128.f - mu1*mu1 + 1e-5f);
            int r0 = bm + rA, r1 = bm + rB;
            #pragma unroll
            for (int j=0;j<8;j++){
                int col = nb + j*8 + t*2;
                float g0 = gam[col], g1 = gam[col+1];
                float e0 = bet[col], e1 = bet[col+1];
                if (r0 < M){
                    float v0 = (acc[mt][j][0]-mu0)*rs0*g0+e0;
                    float v1 = (acc[mt][j][1]-mu0)*rs0*g1+e1;
                    *(float2*)&C[(size_t)r0*EMB + col] = make_float2(v0,v1);
                }
                if (r1 < M){
                    float v0 = (acc[mt][j][2]-mu1)*rs1*g0+e0;
                    float v1 = (acc[mt][j][3]-mu1)*rs1*g1+e1;
                    *(float2*)&C[(size_t)r1*EMB + col] = make_float2(v0,v1);
                }
            }
        }
        __syncthreads();
    }
}

// ---------------- fused branch-1 attention megakernel (double-buffered GEMM stages) ----------------
#define B1A_BUF  17408
#define B1A_SQ   (2*B1A_BUF)
#define B1A_SO   (B1A_SQ + 67584)
#define B1A_SSUM (B1A_SO + 67584)
#define B1A_SSQ  (B1A_SSUM + 1024)
#define B1_SMEM  (B1A_SSQ + 1024)
__global__ void __launch_bounds__(256) k_b1attn(
    const float* __restrict__ se, const float* __restrict__ sp,
    const float* __restrict__ Wq, const float* __restrict__ bq,
    const float* __restrict__ Wo, const float* __restrict__ bo,
    const float* __restrict__ gam, const float* __restrict__ bet,
    float* __restrict__ X)
{
    extern __shared__ unsigned char dsm[];
    typedef unsigned (*SmTile)[SMS];
    SmTile AhB[2], AlB[2], WhB[2], WlB[2];
    #pragma unroll
    for (int bb=0; bb<2; bb++){
        AhB[bb] = (SmTile)(dsm + bb*B1A_BUF + 0);
        AlB[bb] = (SmTile)(dsm + bb*B1A_BUF + 4352);
        WhB[bb] = (SmTile)(dsm + bb*B1A_BUF + 8704);
        WlB[bb] = (SmTile)(dsm + bb*B1A_BUF + 13056);
    }
    float (*sQ)[132]    = (float (*)[132])(dsm + B1A_SQ);
    float (*sO)[132]    = (float (*)[132])(dsm + B1A_SO);
    float (*ssum)[2]    = (float (*)[2])(dsm + B1A_SSUM);
    float (*ssq)[2]     = (float (*)[2])(dsm + B1A_SSQ);

    int M = g_ints[2];
    int Ns = g_ints[1];
    int tid = threadIdx.x;
    int row_l = tid & 127;
    int kq    = (tid >> 7) * 8;
    int w = tid >> 5, lane = tid & 31;
    int g = lane >> 2, t = lane & 3;
    int mb = (w >> 1) * 32, nb = (w & 1) * 64;

    int b = 0;
    for (int bm = blockIdx.y*128; bm < M; bm += gridDim.y*128){
        // ===== stage 1: Qp = (se+sp) @ Wq^T + bq -> sQ =====
        float acc[2][8][4];
        #pragma unroll
        for (int mt=0;mt<2;mt++)
            #pragma unroll
            for (int j=0;j<8;j++)
                #pragma unroll
                for (int q=0;q<4;q++) acc[mt][j][q]=0.f;

        for (int kt=0; kt<EMB; kt+=16){
            {
                int arow = bm + row_l;
                float va[8];
                if (arow < M){
                    const float* pa = &se[(size_t)arow*EMB + kt + kq];
                    const float* pb = &sp[(size_t)arow*EMB + kt + kq];
                    float4 v0 = *(const float4*)pa, v1 = *(const float4*)(pa+4);
                    float4 u0 = *(const float4*)pb, u1 = *(const float4*)(pb+4);
                    va[0]=v0.x+u0.x; va[1]=v0.y+u0.y; va[2]=v0.z+u0.z; va[3]=v0.w+u0.w;
                    va[4]=v1.x+u1.x; va[5]=v1.y+u1.y; va[6]=v1.z+u1.z; va[7]=v1.w+u1.w;
                } else {
                    #pragma unroll
                    for (int j=0;j<8;j++) va[j]=0.f;
                }
                STORE_SPLIT_TO(va, AhB[b], AlB[b]);
                const float* pw = &Wq[(size_t)row_l*EMB + kt + kq];
                float4 w0 = *(const float4*)pw, w1 = *(const float4*)(pw+4);
                float vw[8] = {w0.x,w0.y,w0.z,w0.w,w1.x,w1.y,w1.z,w1.w};
                STORE_SPLIT_TO(vw, WhB[b], WlB[b]);
            }
            __syncthreads();
            LOAD_FRAGS_AND_MMA_FROM(AhB[b], AlB[b], WhB[b], WlB[b]);
            b ^= 1;
        }
        #pragma unroll
        for (int mt=0;mt<2;mt++){
            #pragma unroll
            for (int j=0;j<8;j++){
                int col = nb + j*8 + t*2;
                int ph = ((col>>5)*33) + (col&31);
                float b0v = bq[col], b1v = bq[col+1];
                int rA = mb + mt*16 + g, rB = rA + 8;
                sQ[rA][ph]   = acc[mt][j][0] + b0v;
                sQ[rA][ph+1] = acc[mt][j][1] + b1v;
                sQ[rB][ph]   = acc[mt][j][2] + b0v;
                sQ[rB][ph+1] = acc[mt][j][3] + b1v;
            }
        }
        __syncthreads();

        // ===== stage 2: per-row per-head attention over Ns inst keys =====
        #pragma unroll
        for (int half=0; half<2; half++){
            int row = half*64 + (tid>>2);
            int h = tid & 3;
            int pb = h*33;
            float m = NEGV, l = 0.f, pacc[32];
            #pragma unroll
            for (int d=0;d<32;d++) pacc[d]=0.f;
            for (int j=0;j<Ns;j++){
                const float* kr = &gi_Kp[j*EMB + h*32];
                float dsum = 0.f;
                #pragma unroll
                for (int d=0;d<32;d++) dsum += sQ[row][pb+d]*kr[d];
                dsum *= 0.17677669529663687f;
                float nm = fmaxf(m, dsum);
                float fac = expf(m-nm), e = expf(dsum-nm);
                l = l*fac + e;
                const float* vr = &gi_Vp[j*EMB + h*32];
                #pragma unroll
                for (int d=0;d<32;d++) pacc[d] = pacc[d]*fac + e*vr[d];
                m = nm;
            }
            float inv = 1.f/l;
            #pragma unroll
            for (int d=0;d<32;d++) sO[row][h*32+d] = pacc[d]*inv;
        }
        __syncthreads();

        // ===== stage 3: out = sO @ Wo^T + bo; x = LN(se+sp+out) =====
        #pragma unroll
        for (int mt=0;mt<2;mt++)
            #pragma unroll
            for (int j=0;j<8;j++)
                #pragma unroll
                for (int q=0;q<4;q++) acc[mt][j][q]=0.f;

        for (int kt=0; kt<EMB; kt+=16){
            {
                float va[8];
                #pragma unroll
                for (int j=0;j<8;j++) va[j] = sO[row_l][kt+kq+j];
                STORE_SPLIT_TO(va, AhB[b], AlB[b]);
                const float* pw = &Wo[(size_t)row_l*EMB + kt + kq];
                float4 w0 = *(const float4*)pw, w1 = *(const float4*)(pw+4);
                float vw[8] = {w0.x,w0.y,w0.z,w0.w,w1.x,w1.y,w1.z,w1.w};
                STORE_SPLIT_TO(vw, WhB[b], WlB[b]);
            }
            __syncthreads();
            LOAD_FRAGS_AND_MMA_FROM(AhB[b], AlB[b], WhB[b], WlB[b]);
            b ^= 1;
        }
        #pragma unroll
        for (int mt=0;mt<2;mt++){
            #pragma unroll
            for (int j=0;j<8;j++){
                int col = nb + j*8 + t*2;
                float b0v = bo[col], b1v = bo[col+1];
                int r0 = bm + mb + mt*16 + g, r1 = r0 + 8;
                size_t o0 = (size_t)min(r0, M-1)*EMB + col;
                size_t o1 = (size_t)min(r1, M-1)*EMB + col;
                float a0 = acc[mt][j][0] + b0v + se[o0] + sp[o0];
                float a1 = acc[mt][j][1] + b1v + se[o0+1] + sp[o0+1];
                float a2 = acc[mt][j][2] + b0v + se[o1] + sp[o1];
                float a3 = acc[mt][j][3] + b1v + se[o1+1] + sp[o1+1];
                acc[mt][j][0]=a0; acc[mt][j][1]=a1; acc[mt][j][2]=a2; acc[mt][j][3]=a3;
            }
        }
        float s_[2][2], q_[2][2];
        #pragma unroll
        for (int mt=0;mt<2;mt++){
            s_[mt][0]=0.f; s_[mt][1]=0.f; q_[mt][0]=0.f; q_[mt][1]=0.f;
            #pragma unroll
            for (int j=0;j<8;j++){
                s_[mt][0]+=acc[mt][j][0]+acc[mt][j][1];
                q_[mt][0]+=acc[mt][j][0]*acc[mt][j][0]+acc[mt][j][1]*acc[mt][j][1];
                s_[mt][1]+=acc[mt][j][2]+acc[mt][j][3];
                q_[mt][1]+=acc[mt][j][2]*acc[mt][j][2]+acc[mt][j][3]*acc[mt][j][3];
            }
        }
        #pragma unroll
        for (int off=1; off<4; off<<=1){
            #pragma unroll
            for (int mt=0;mt<2;mt++){
                s_[mt][0]+=__shfl_xor_sync(0xffffffffu, s_[mt][0], off);
                s_[mt][1]+=__shfl_xor_sync(0xffffffffu, s_[mt][1], off);
                q_[mt][0]+=__shfl_xor_sync(0xffffffffu, q_[mt][0], off);
                q_[mt][1]+=__shfl_xor_sync(0xffffffffu, q_[mt][1], off);
            }
        }
        if (t == 0){
            #pragma unroll
            for (int mt=0;mt<2;mt++){
                int rA = mb + mt*16 + g, rB = rA + 8;
                ssum[rA][w&1]=s_[mt][0]; ssq[rA][w&1]=q_[mt][0];
                ssum[rB][w&1]=s_[mt][1]; ssq[rB][w&1]=q_[mt][1];
            }
        }
        __syncthreads();
        #pragma unroll
        for (int mt=0;mt<2;mt++){
            int rA = mb + mt*16 + g, rB = rA + 8;
            float su0 = ssum[rA][0]+ssum[rA][1], sq0 = ssq[rA][0]+ssq[rA][1];
            float su1 = ssum[rB][0]+ssum[rB][1], sq1 = ssq[rB][0]+ssq[rB][1];
            float mu0 = su0/128.f, mu1 = su1/128.f;
            float rs0 = rsqrtf(sq0/128.f - mu0*mu0 + 1e-5f);
            float rs1 = rsqrtf(sq1/128.f - mu1*mu1 + 1e-5f);
            int r0 = bm + rA, r1 = bm + rB;
            #pragma unroll
            for (int j=0;j<8;j++){
                int col = nb + j*8 + t*2;
                float g0 = gam[col], g1 = gam[col+1];
                float e0 = bet[col], e1 = bet[col+1];
                if (r0 < M){
                    float v0 = (acc[mt][j][0]-mu0)*rs0*g0+e0;
                    float v1 = (acc[mt][j][1]-mu0)*rs0*g1+e1;
                    *(float2*)&X[(size_t)r0*EMB + col] = make_float2(v0,v1);
                }
                if (r1 < M){
                    float v0 = (acc[mt][j][2]-mu1)*rs1*g0+e0;
                    float v1 = (acc[mt][j][3]-mu1)*rs1*g1+e1;
                    *(float2*)&X[(size_t)r1*EMB + col] = make_float2(v0,v1);
                }
            }
        }
        __syncthreads();
    }
}

// ---------------- fused instance-side kernels ----------------
__device__ __forceinline__ float block_ln(float x, float* red, int t,
                                          const float* g, const float* b){
    red[t]=x; __syncthreads();
    for (int off=64; off>0; off>>=1){ if (t<off) red[t]+=red[t+off]; __syncthreads(); }
    float mu = red[0]/128.f; __syncthreads();
    float d = x-mu;
    red[t]=d*d; __syncthreads();
    for (int off=64; off>0; off>>=1){ if (t<off) red[t]+=red[t+off]; __syncthreads(); }
    float var = red[0]/128.f; __syncthreads();
    return d*rsqrtf(var+1e-5f)*g[t]+b[t];
}

__global__ void k_inst_pre(const float* __restrict__ wq, const float* __restrict__ bq){
    int s = blockIdx.x;
    if (s >= g_ints[1]) return;
    int c = threadIdx.x;
    __shared__ float sq_[EMB];
    float qin = gi_q[s*EMB+c] + gi_p[s*EMB+c];
    gi_qin[s*EMB+c] = qin;
    sq_[c] = qin; __syncthreads();
    float acc = bq[c];
    const float* wr = &wq[c*EMB];
    #pragma unroll 8
    for (int k=0;k<EMB;k++) acc += sq_[k]*wr[k];
    gi_Qp[s*EMB+c] = acc;
}

__global__ void k_inst_kv(const float* __restrict__ wk, const float* __restrict__ bk,
                          const float* __restrict__ wv, const float* __restrict__ bv){
    int s = blockIdx.x;
    if (s >= g_ints[1]) return;
    int c = threadIdx.x;
    __shared__ float sqin[EMB], sq_[EMB];
    float qv = gi_q[s*EMB+c];
    sqin[c] = qv + gi_p[s*EMB+c];
    sq_[c]  = qv;
    __syncthreads();
    float ak = bk[c], av = bv[c];
    const float* wkr = &wk[c*EMB];
    const float* wvr = &wv[c*EMB];
    #pragma unroll 8
    for (int k=0;k<EMB;k++){ ak += sqin[k]*wkr[k]; av += sq_[k]*wvr[k]; }
    gi_Kp[s*EMB+c] = ak;
    gi_Vp[s*EMB+c] = av;
}

__global__ void k_inst_post(const float* __restrict__ wo, const float* __restrict__ bo,
                            const float* __restrict__ lg, const float* __restrict__ lb,
                            const float* __restrict__ w1, const float* __restrict__ b1,
                            const float* __restrict__ w2, const float* __restrict__ b2){
    int s = blockIdx.x;
    if (s >= g_ints[1]) return;
    int c = threadIdx.x;
    __shared__ float sO[EMB], sx[EMB], sh[HIDN], red[EMB];
    {
        int h = c>>5, lane = c&31;
        float m = NEGV, l = 0.f, a = 0.f;
        int base = (h*NIM + s)*16;
        for (int ck=0;ck<16;ck++){
            float mc = g_pm[base+ck], lc = g_pl[base+ck];
            float ac = g_pacc[(size_t)(base+ck)*32 + lane];
            float nm = fmaxf(m, mc);
            float fa = expf(m-nm), fb = expf(mc-nm);
            l = l*fa + lc*fb;
            a = a*fa + ac*fb;
            m = nm;
        }
        sO[c] = a/l;
    }
    __syncthreads();
    float mha = bo[c];
    {
        const float* wr = &wo[c*EMB];
        #pragma unroll 8
        for (int k=0;k<EMB;k++) mha += sO[k]*wr[k];
    }
    float x = block_ln(gi_qin[s*EMB+c] + mha, red, c, lg, lb);
    sx[c] = x; __syncthreads();
    #pragma unroll
    for (int hc=c; hc<HIDN; hc+=EMB){
        float a = b1[hc];
        const float* wr = &w1[hc*EMB];
        #pragma unroll 8
        for (int k=0;k<EMB;k++) a += sx[k]*wr[k];
        sh[hc] = fmaxf(a, 0.f);
    }
    __syncthreads();
    float h2 = b2[c];
    {
        const float* wr = &w2[c*HIDN];
        #pragma unroll 8
        for (int k=0;k<HIDN;k++) h2 += sh[k]*wr[k];
    }
    gi_q[s*EMB+c] = block_ln(x + h2, red, c, lg+EMB, lb+EMB);
}

// ---------------- attn0: 8 instances per block, smem-staged K/V ----------------
__global__ void __launch_bounds__(256) k_attn0p(
    const float* __restrict__ Kp, const float* __restrict__ Vp)
{
    int Ns = g_ints[1];
    int grp = blockIdx.z;
    if (grp*8 >= Ns) return;
    int h = blockIdx.y;
    int c = blockIdx.x;           // 0..15
    int Nf = g_ints[2];
    int chunk = (Nf + 15) >> 4;
    int k0 = c*chunk, k1 = min(k0+chunk, Nf);
    int tid = threadIdx.x;
    int is = tid >> 5, kl = tid & 31;
    int s = grp*8 + is;
    bool sok = (s < Ns);

    __shared__ float sK[32][33], sV[32][33];
    __shared__ float sq[8][33];
    if (sok) sq[is][kl] = gi_Qp[s*EMB + h*32 + kl] * 0.17677669529663687f;
    __syncthreads();

    float m = NEGV, l = 0.f, acc[32];
    #pragma unroll
    for (int d=0;d<32;d++) acc[d]=0.f;

    for (int kp0 = k0; kp0 < k1; kp0 += 32){
        int nk = min(32, k1 - kp0);
        for (int idx = tid; idx < nk*32; idx += 256){
            int kr = idx >> 5, d = idx & 31;
            sK[kr][d] = Kp[(size_t)(kp0+kr)*EMB + h*32 + d];
            sV[kr][d] = Vp[(size_t)(kp0+kr)*EMB + h*32 + d];
        }
        __syncthreads();
        if (sok && kl < nk){
            float dsum = 0.f;
            #pragma unroll
            for (int d=0;d<32;d++) dsum += sq[is][d]*sK[kl][d];
            float nm = fmaxf(m, dsum);
            float fac = expf(m - nm);
            float e = expf(dsum - nm);
            l = l*fac + e;
            #pragma unroll
            for (int d=0;d<32;d++) acc[d] = acc[d]*fac + e*sV[kl][d];
            m = nm;
        }
        __syncthreads();
    }

    #pragma unroll
    for (int off=16; off>0; off>>=1){
        float mo = __shfl_xor_sync(0xffffffffu, m, off);
        float lo = __shfl_xor_sync(0xffffffffu, l, off);
        float nm = fmaxf(m, mo);
        float fa = expf(m-nm), fb = expf(mo-nm);
        l = l*fa + lo*fb;
        #pragma unroll
        for (int d=0;d<32;d++){
            float ao = __shfl_xor_sync(0xffffffffu, acc[d], off);
            acc[d] = acc[d]*fa + ao*fb;
        }
        m = nm;
    }

    if (sok){
        int pi = (h*NIM + s)*16 + c;
        if (kl == 0){ g_pm[pi] = m; g_pl[pi] = l; }
        #pragma unroll
        for (int d=0;d<32;d++)
            if (kl == d) g_pacc[(size_t)pi*32 + d] = acc[d];
    }
}

// ---------------- final conv (with inline scatter of se) ----------------
__global__ void __launch_bounds__(256) k_conv(
    const void* __restrict__ fm,
    const float* __restrict__ cw, const float* __restrict__ cb,
    float* __restrict__ out)
{
    __shared__ float scw[20*EMB];
    __shared__ float scb[20];
    for (int i=threadIdx.x; i<20*EMB; i+=256) scw[i]=cw[i];
    if (threadIdx.x < 20) scb[threadIdx.x]=cb[threadIdx.x];
    __syncthreads();
    int n = blockIdx.x*256 + threadIdx.x;
    const float* row;
    if (fov_get(fm, n)) row = &g_se[(size_t)g_inv[n]*EMB];
    else                row = &g_full[(size_t)n*EMB];
    float r[EMB/4][4];
    #pragma unroll
    for (int k=0;k<EMB/4;k++) *(float4*)r[k] = *(const float4*)&row[k*4];
    for (int o=0;o<20;o++){
        float acc = scb[o];
        const float* w = &scw[o*EMB];
        #pragma unroll
        for (int k=0;k<EMB;k++) acc += r[k>>2][k&3]*w[k];
        out[(size_t)o*NQv + n] = acc;
    }
}

// ---------------- host ----------------
extern "C" void kernel_launch(void* const* d_in, const int* in_sizes, int n_in,
                              void* d_out, int out_size)
{
    const float* queries  = (const float*)d_in[0];
    const float* logits   = (const float*)d_in[1];
    const float* pmasks   = (const float*)d_in[2];
    const float* x3d      = (const float*)d_in[3];
    const float* depth    = (const float*)d_in[4];
    const float* Km       = (const float*)d_in[5];
    const float* Em       = (const float*)d_in[6];
    const float* vo       = (const float*)d_in[7];
    const void * fov      = (const void *)d_in[8];
    const float* sew      = (const float*)d_in[9];
    const float* instposw = (const float*)d_in[10];
    const float* posw     = (const float*)d_in[11];
    const float* convw    = (const float*)d_in[12];
    const float* convb    = (const float*)d_in[13];
    const float* attw     = (const float*)d_in[14];
    const float* attb     = (const float*)d_in[15];
    const float* lng      = (const float*)d_in[16];
    const float* lnb      = (const float*)d_in[17];
    const float* fw1      = (const float*)d_in[18];
    const float* fb1      = (const float*)d_in[19];
    const float* fw2      = (const float*)d_in[20];
    const float* fb2      = (const float*)d_in[21];
    float* out = (float*)d_out;

    float *p_se, *p_sp, *p_bA, *p_hid;
    cudaGetSymbolAddress((void**)&p_se,  g_se);
    cudaGetSymbolAddress((void**)&p_sp,  g_sp);
    cudaGetSymbolAddress((void**)&p_bA,  g_bA);
    cudaGetSymbolAddress((void**)&p_hid, g_hid);

    cudaFuncSetAttribute(k_b1attn, cudaFuncAttributeMaxDynamicSharedMemorySize, B1_SMEM);

    const size_t E2 = (size_t)EMB*EMB;

    // fov + scene setup
    k_fovdetect<<<1,256>>>((const unsigned int*)fov);
    k_fovcount<<<512,512>>>(fov);
    k_fovscan<<<1,512>>>();
    k_fovscatter<<<512,512>>>(fov);
    dim3 tb(32,8);
    k_buildfull<<<dim3(NQv/32,4),tb>>>(fov, sew, x3d, posw, vo);

    // instance post-processing
    k_world<<<(HWPX+255)/256,256>>>(depth, Km, Em);
    k_scores<<<1,320>>>(logits);
    k_mids<<<(HWPX+255)/256,256>>>(pmasks);
    k_areas<<<NIc,256>>>(pmasks);
    k_select<<<1,1>>>();
    k_xyz<<<NIc,256>>>(pmasks);
    k_instbuild<<<NIc,128>>>(queries, instposw, posw);

    for (int i=0;i<2;i++){
        // ---- branch 0: update inst queries (attend to scene) ----
        const float* aw = attw + (size_t)(i*2+0)*4*E2;
        const float* ab = attb + (size_t)(i*2+0)*4*EMB;
        const float* g0 = lng + (size_t)(i*2+0)*2*EMB;
        const float* b0 = lnb + (size_t)(i*2+0)*2*EMB;
        k_inst_pre<<<NIc,128>>>(aw+0*E2, ab+0*EMB);
        k_gemm<<<dim3(2,148),256>>>(p_se, p_sp, 128, aw+1*E2, ab+1*EMB,
                                    p_bA, p_hid, 256, EMB, 0, EMB);   // Kp->bA, Vp->hid
        k_attn0p<<<dim3(16,4,(NIc+7)/8),256>>>(p_bA, p_hid);
        k_inst_post<<<NIc,128>>>(aw+3*E2, ab+3*EMB, g0, b0,
                                 fw1+(size_t)(i*2+0)*HIDN*EMB, fb1+(size_t)(i*2+0)*HIDN,
                                 fw2+(size_t)(i*2+0)*EMB*HIDN, fb2+(size_t)(i*2+0)*EMB);

        // ---- branch 1: update scene embeddings (attend to inst) ----
        aw = attw + (size_t)(i*2+1)*4*E2;
        ab = attb + (size_t)(i*2+1)*4*EMB;
        const float* g1v = lng + (size_t)(i*2+1)*2*EMB;
        const float* b1v = lnb + (size_t)(i*2+1)*2*EMB;
        k_inst_kv<<<NIc,128>>>(aw+1*E2, ab+1*EMB, aw+2*E2, ab+2*EMB);
        k_b1attn<<<dim3(1,512),256,B1_SMEM>>>(p_se, p_sp,
                                              aw+0*E2, ab+0*EMB,
                                              aw+3*E2, ab+3*EMB,
                                              g1v, b1v, p_bA);        // x -> bA
        k_gemm<<<dim3(4,148),256>>>(p_bA, NULL, 0,
                                    fw1+(size_t)(i*2+1)*HIDN*EMB, fb1+(size_t)(i*2+1)*HIDN,
                                    p_hid, NULL, HIDN, EMB, 1, HIDN);
        k_gemm_ln<<<dim3(1,296),256>>>(p_hid,
                                       fw2+(size_t)(i*2+1)*EMB*HIDN, fb2+(size_t)(i*2+1)*EMB,
                                       p_bA, NULL, g1v+EMB, b1v+EMB, p_se, HIDN);
    }

    k_conv<<<NQv/256,256>>>(fov, convw, convb, out);
}